// round 1
// baseline (speedup 1.0000x reference)
#include <cuda_runtime.h>
#include <math.h>

#define BB 16
#define LBL 48
#define PRED 336
#define LSEQ 384
#define CIN 7
#define TFD 4
#define DM 512
#define DIN 1024
#define NST 16
#define DTR 32
#define DCONV 4
#define NLAYER 2
#define EPSF 1e-5f

#define NTOK (BB*LSEQ)   // 6144 rows

// ------------------- scratch (static device globals; no allocs) -------------
__device__ float g_x  [NTOK*DM];
__device__ float g_xn [NTOK*DM];
__device__ float g_xz [NTOK*2*DIN];
__device__ float g_xc [NTOK*DIN];
__device__ float g_dbc[NTOK*64];
__device__ float g_dt [NTOK*DIN];
__device__ float g_y  [NTOK*DIN];
__device__ float g_mean[BB*CIN];
__device__ float g_std [BB*CIN];

// ------------------------------- helpers ------------------------------------
__device__ __forceinline__ float block_reduce_sum(float v, float* red) {
    __syncthreads();                       // protect red from previous use
    int lane = threadIdx.x & 31, wid = threadIdx.x >> 5;
    #pragma unroll
    for (int o = 16; o; o >>= 1) v += __shfl_xor_sync(0xffffffffu, v, o);
    if (lane == 0) red[wid] = v;
    __syncthreads();
    if (wid == 0) {
        float t = (lane < (int)(blockDim.x >> 5)) ? red[lane] : 0.f;
        #pragma unroll
        for (int o = 16; o; o >>= 1) t += __shfl_xor_sync(0xffffffffu, t, o);
        if (lane == 0) red[0] = t;
    }
    __syncthreads();
    return red[0];
}

__device__ __forceinline__ float siluf(float x) {
    return x / (1.f + expf(-x));
}

// --------------------- mean/std over label window ---------------------------
__global__ void meanstd_kernel(const float* __restrict__ x_dec,
                               float* __restrict__ mean, float* __restrict__ stdv) {
    int i = threadIdx.x;
    if (i >= BB*CIN) return;
    int b = i / CIN, c = i % CIN;
    float s = 0.f;
    for (int t = 0; t < LBL; t++) s += x_dec[(b*LSEQ + t)*CIN + c];
    float m = s / (float)LBL;
    float v = 0.f;
    for (int t = 0; t < LBL; t++) {
        float d = x_dec[(b*LSEQ + t)*CIN + c] - m;
        v += d*d;
    }
    v /= (float)LBL;
    mean[i] = m;
    stdv[i] = sqrtf(v + EPSF);
}

// ---------------- token embed (circular conv k=3) + time features -----------
__global__ void embed_kernel(const float* __restrict__ x_dec,
                             const float* __restrict__ mark,
                             const float* __restrict__ token_w,  // (DM,CIN,3)
                             const float* __restrict__ timef_w,  // (DM,TFD)
                             const float* __restrict__ mean,
                             const float* __restrict__ stdv,
                             float* __restrict__ x) {
    int t = blockIdx.x, b = blockIdx.y;
    int m = threadIdx.x;                 // 512 threads
    __shared__ float xs[3][CIN];
    __shared__ float ms[TFD];
    if (threadIdx.x < 3*CIN) {
        int k = threadIdx.x / CIN, c = threadIdx.x % CIN;
        int s = (t - 1 + k + LSEQ) % LSEQ;
        float v = x_dec[(b*LSEQ + s)*CIN + c];
        if (s < LBL) v = (v - mean[b*CIN + c]) / stdv[b*CIN + c];
        xs[k][c] = v;
    }
    if (threadIdx.x >= 32 && threadIdx.x < 32 + TFD)
        ms[threadIdx.x - 32] = mark[(b*LSEQ + t)*TFD + threadIdx.x - 32];
    __syncthreads();
    float acc = 0.f;
    #pragma unroll
    for (int c = 0; c < CIN; c++)
        #pragma unroll
        for (int k = 0; k < 3; k++)
            acc += xs[k][c] * token_w[(m*CIN + c)*3 + k];
    #pragma unroll
    for (int f = 0; f < TFD; f++) acc += ms[f] * timef_w[m*TFD + f];
    x[((size_t)(b*LSEQ + t))*DM + m] = acc;
}

// --------------------------- layernorm (rows of DM) -------------------------
__global__ void ln_kernel(const float* __restrict__ x,
                          const float* __restrict__ w,
                          const float* __restrict__ bb,
                          float* __restrict__ out) {
    __shared__ float red[32];
    int row = blockIdx.x;
    const float* xr = x + (size_t)row*DM;
    int tid = threadIdx.x;               // 256 threads, 2 elems each
    float v0 = xr[tid], v1 = xr[tid + 256];
    float s = block_reduce_sum(v0 + v1, red);
    float m = s * (1.f/(float)DM);
    float d0 = v0 - m, d1 = v1 - m;
    float vs = block_reduce_sum(d0*d0 + d1*d1, red);
    float inv = rsqrtf(vs * (1.f/(float)DM) + EPSF);
    out[(size_t)row*DM + tid]       = d0*inv*w[tid]       + bb[tid];
    out[(size_t)row*DM + tid + 256] = d1*inv*w[tid + 256] + bb[tid + 256];
}

// ------------------------------ generic SGEMM -------------------------------
// C[M,N] = op(A[M,K(lda)] @ W[N,K]^T), mode: 0 store, 1 softplus(v+bias) store,
// 2 accumulate into C (residual).
template<int BM, int BN, int BK, int TM, int TN>
__global__ void gemm_kernel(const float* __restrict__ A, int lda,
                            const float* __restrict__ W,
                            const float* __restrict__ bias,
                            float* __restrict__ C, int ldc,
                            int M, int Nn, int K, int mode) {
    constexpr int THREADS = (BM/TM)*(BN/TN);
    __shared__ float As[BK][BM];
    __shared__ float Bs[BK][BN];
    int tid = threadIdx.x;
    int tx = tid % (BN/TN);
    int ty = tid / (BN/TN);
    int row0 = blockIdx.y * BM;
    int col0 = blockIdx.x * BN;
    float acc[TM][TN];
    #pragma unroll
    for (int i = 0; i < TM; i++)
        #pragma unroll
        for (int j = 0; j < TN; j++) acc[i][j] = 0.f;

    for (int k0 = 0; k0 < K; k0 += BK) {
        #pragma unroll
        for (int i = tid; i < BM*BK; i += THREADS) {
            int m = i / BK, kk = i % BK;
            As[kk][m] = A[(size_t)(row0 + m)*lda + k0 + kk];
        }
        #pragma unroll
        for (int i = tid; i < BN*BK; i += THREADS) {
            int n = i / BK, kk = i % BK;
            Bs[kk][n] = W[(size_t)(col0 + n)*K + k0 + kk];
        }
        __syncthreads();
        #pragma unroll
        for (int kk = 0; kk < BK; kk++) {
            float a[TM], bfr[TN];
            #pragma unroll
            for (int i = 0; i < TM; i++) a[i] = As[kk][ty*TM + i];
            #pragma unroll
            for (int j = 0; j < TN; j++) bfr[j] = Bs[kk][tx*TN + j];
            #pragma unroll
            for (int i = 0; i < TM; i++)
                #pragma unroll
                for (int j = 0; j < TN; j++) acc[i][j] += a[i]*bfr[j];
        }
        __syncthreads();
    }
    #pragma unroll
    for (int i = 0; i < TM; i++) {
        int gm = row0 + ty*TM + i;
        #pragma unroll
        for (int j = 0; j < TN; j++) {
            int gn = col0 + tx*TN + j;
            float v = acc[i][j];
            if (mode == 1) {
                v += bias[gn];
                v = (v > 20.f) ? v : log1pf(expf(v));
            }
            if (mode == 2) C[(size_t)gm*ldc + gn] += v;
            else           C[(size_t)gm*ldc + gn]  = v;
        }
    }
}

// -------------------- depthwise causal conv (k=4) + SiLU --------------------
__global__ void dwconv_kernel(const float* __restrict__ xz,   // (B,L,2*DIN) first half
                              const float* __restrict__ w,    // (DIN,1,4)
                              const float* __restrict__ bias, // (DIN)
                              float* __restrict__ xc) {       // (B,L,DIN)
    int gid = blockIdx.x * blockDim.x + threadIdx.x;
    int d = gid % DIN;
    int t = (gid / DIN) % LSEQ;
    int b = gid / (DIN * LSEQ);
    const float* xin = xz + (size_t)b * LSEQ * 2 * DIN;
    float acc = bias[d];
    #pragma unroll
    for (int k = 0; k < DCONV; k++) {
        int s = t - (DCONV-1) + k;
        if (s >= 0) acc += xin[(size_t)s*2*DIN + d] * w[d*DCONV + k];
    }
    xc[gid] = siluf(acc);
}

// --------------------------- selective scan ---------------------------------
// thread = (b, d, n); 16-lane shuffle reduce over n; fused (y+u*D)*silu(z).
__global__ void scan_kernel(const float* __restrict__ xc,    // (B,L,DIN)
                            const float* __restrict__ dt,    // (B,L,DIN)
                            const float* __restrict__ dbc,   // (B,L,64): [dt_r|B|C]
                            const float* __restrict__ A_log, // (DIN,NST)
                            const float* __restrict__ Dp,    // (DIN)
                            const float* __restrict__ xz,    // (B,L,2*DIN), z at +DIN
                            float* __restrict__ y) {         // (B,L,DIN)
    int gid = blockIdx.x * blockDim.x + threadIdx.x;
    int n = gid & (NST - 1);
    int d = (gid >> 4) & (DIN - 1);
    int b = gid >> 14;
    float a  = -expf(A_log[d*NST + n]);
    float Dd = Dp[d];
    float h  = 0.f;
    const float* dbc_b = dbc + (size_t)b * LSEQ * 64;
    size_t base = (size_t)b * LSEQ * DIN + d;
    size_t zbase = (size_t)b * LSEQ * 2 * DIN + DIN + d;
    for (int t = 0; t < LSEQ; t++) {
        float dtv = dt[base + (size_t)t*DIN];
        float uv  = xc[base + (size_t)t*DIN];
        float Bv  = dbc_b[t*64 + DTR + n];
        float Cv  = dbc_b[t*64 + DTR + NST + n];
        float dA  = expf(dtv * a);
        h = dA*h + (dtv*uv)*Bv;
        float p = h * Cv;
        p += __shfl_xor_sync(0xffffffffu, p, 8);
        p += __shfl_xor_sync(0xffffffffu, p, 4);
        p += __shfl_xor_sync(0xffffffffu, p, 2);
        p += __shfl_xor_sync(0xffffffffu, p, 1);
        if (n == 0) {
            float zv = xz[zbase + (size_t)t*2*DIN];
            y[base + (size_t)t*DIN] = (p + uv*Dd) * siluf(zv);
        }
    }
}

// ------------------------- output head + denorm -----------------------------
__global__ void out_kernel(const float* __restrict__ xn,     // (B,L,DM) after final LN
                           const float* __restrict__ out_w,  // (CIN,DM)
                           const float* __restrict__ mean,
                           const float* __restrict__ stdv,
                           float* __restrict__ out) {        // (B,PRED,CIN)
    int t_out = blockIdx.x, b = blockIdx.y;
    int t = LBL + t_out;
    __shared__ float row[DM];
    for (int i = threadIdx.x; i < DM; i += blockDim.x)
        row[i] = xn[((size_t)(b*LSEQ + t))*DM + i];
    __syncthreads();
    int c = threadIdx.x >> 5;
    int lane = threadIdx.x & 31;
    if (c < CIN) {
        float acc = 0.f;
        for (int i = lane; i < DM; i += 32) acc += row[i] * out_w[c*DM + i];
        #pragma unroll
        for (int o = 16; o; o >>= 1) acc += __shfl_xor_sync(0xffffffffu, acc, o);
        if (lane == 0)
            out[(size_t)(b*PRED + t_out)*CIN + c] = acc * stdv[b*CIN + c] + mean[b*CIN + c];
    }
}

// ------------------------------- launcher -----------------------------------
extern "C" void kernel_launch(void* const* d_in, const int* in_sizes, int n_in,
                              void* d_out, int out_size) {
    const float* x_dec    = (const float*)d_in[2];
    const float* mark     = (const float*)d_in[3];
    const float* token_w  = (const float*)d_in[4];
    const float* timef_w  = (const float*)d_in[5];
    const float* norm_w   = (const float*)d_in[6];
    const float* norm_b   = (const float*)d_in[7];
    const float* in_proj_w= (const float*)d_in[8];
    const float* conv_w   = (const float*)d_in[9];
    const float* conv_b   = (const float*)d_in[10];
    const float* xproj_w  = (const float*)d_in[11];
    const float* dtproj_w = (const float*)d_in[12];
    const float* dtproj_b = (const float*)d_in[13];
    const float* A_log    = (const float*)d_in[14];
    const float* Dp       = (const float*)d_in[15];
    const float* outproj_w= (const float*)d_in[16];
    const float* fin_w    = (const float*)d_in[17];
    const float* fin_b    = (const float*)d_in[18];
    const float* out_w    = (const float*)d_in[19];
    float* out = (float*)d_out;

    float *px, *pxn, *pxz, *pxc, *pdbc, *pdt, *py, *pmean, *pstd;
    cudaGetSymbolAddress((void**)&px,   g_x);
    cudaGetSymbolAddress((void**)&pxn,  g_xn);
    cudaGetSymbolAddress((void**)&pxz,  g_xz);
    cudaGetSymbolAddress((void**)&pxc,  g_xc);
    cudaGetSymbolAddress((void**)&pdbc, g_dbc);
    cudaGetSymbolAddress((void**)&pdt,  g_dt);
    cudaGetSymbolAddress((void**)&py,   g_y);
    cudaGetSymbolAddress((void**)&pmean,g_mean);
    cudaGetSymbolAddress((void**)&pstd, g_std);

    meanstd_kernel<<<1, 128>>>(x_dec, pmean, pstd);
    embed_kernel<<<dim3(LSEQ, BB), DM>>>(x_dec, mark, token_w, timef_w, pmean, pstd, px);

    for (int l = 0; l < NLAYER; l++) {
        ln_kernel<<<NTOK, 256>>>(px, norm_w + l*DM, norm_b + l*DM, pxn);
        // in_proj: (6144x512) @ (2048x512)^T -> (6144x2048)
        gemm_kernel<128,64,16,8,4><<<dim3(2*DIN/64, NTOK/128), 256>>>(
            pxn, DM, in_proj_w + (size_t)l*2*DIN*DM, nullptr, pxz, 2*DIN,
            NTOK, 2*DIN, DM, 0);
        dwconv_kernel<<<(NTOK*DIN)/256, 256>>>(pxz, conv_w + l*DIN*DCONV,
                                               conv_b + l*DIN, pxc);
        // x_proj: (6144x1024) @ (64x1024)^T -> (6144x64)
        gemm_kernel<64,64,16,4,4><<<dim3(1, NTOK/64), 256>>>(
            pxc, DIN, xproj_w + (size_t)l*64*DIN, nullptr, pdbc, 64,
            NTOK, 64, DIN, 0);
        // dt_proj: (6144x32) @ (1024x32)^T + bias, softplus -> (6144x1024)
        gemm_kernel<64,64,16,4,4><<<dim3(DIN/64, NTOK/64), 256>>>(
            pdbc, 64, dtproj_w + (size_t)l*DIN*DTR, dtproj_b + l*DIN, pdt, DIN,
            NTOK, DIN, DTR, 1);
        scan_kernel<<<(BB*DIN*NST)/256, 256>>>(pxc, pdt, pdbc,
                                               A_log + (size_t)l*DIN*NST,
                                               Dp + l*DIN, pxz, py);
        // out_proj (+residual): (6144x1024) @ (512x1024)^T -> += x
        gemm_kernel<128,64,16,8,4><<<dim3(DM/64, NTOK/128), 256>>>(
            py, DIN, outproj_w + (size_t)l*DM*DIN, nullptr, px, DM,
            NTOK, DM, DIN, 2);
    }

    ln_kernel<<<NTOK, 256>>>(px, fin_w, fin_b, pxn);
    out_kernel<<<dim3(PRED, BB), CIN*32>>>(pxn, out_w, pmean, pstd, out);
}

// round 4
// speedup vs baseline: 1.8727x; 1.8727x over previous
#include <cuda_runtime.h>
#include <stdint.h>
#include <math.h>

#define BB 16
#define LBL 48
#define PRED 336
#define LSEQ 384
#define CIN 7
#define TFD 4
#define DM 512
#define DIN 1024
#define NST 16
#define DTR 32
#define DCONV 4
#define NLAYER 2
#define EPSF 1e-5f

#define NTOK (BB*LSEQ)   // 6144 rows

// ------------------- scratch (static device globals; no allocs) -------------
__device__ float g_x  [NTOK*DM];
__device__ float g_xn [NTOK*DM];
__device__ float g_xz [NTOK*2*DIN];
__device__ float g_xc [NTOK*DIN];
__device__ float g_dbc[NTOK*64];
__device__ float g_dt [NTOK*DIN];
__device__ float g_y  [NTOK*DIN];
__device__ float g_mean[BB*CIN];
__device__ float g_std [BB*CIN];

// ------------------------------- helpers ------------------------------------
__device__ __forceinline__ float block_reduce_sum(float v, float* red) {
    __syncthreads();
    int lane = threadIdx.x & 31, wid = threadIdx.x >> 5;
    #pragma unroll
    for (int o = 16; o; o >>= 1) v += __shfl_xor_sync(0xffffffffu, v, o);
    if (lane == 0) red[wid] = v;
    __syncthreads();
    if (wid == 0) {
        float t = (lane < (int)(blockDim.x >> 5)) ? red[lane] : 0.f;
        #pragma unroll
        for (int o = 16; o; o >>= 1) t += __shfl_xor_sync(0xffffffffu, t, o);
        if (lane == 0) red[0] = t;
    }
    __syncthreads();
    return red[0];
}

__device__ __forceinline__ float siluf(float x) {
    return x / (1.f + expf(-x));
}

__device__ __forceinline__ float tf32r(float x) {
    unsigned int u;
    asm("cvt.rna.tf32.f32 %0, %1;" : "=r"(u) : "f"(x));
    return __uint_as_float(u);
}

// --------------------- mean/std over label window ---------------------------
__global__ void meanstd_kernel(const float* __restrict__ x_dec,
                               float* __restrict__ mean, float* __restrict__ stdv) {
    int i = threadIdx.x;
    if (i >= BB*CIN) return;
    int b = i / CIN, c = i % CIN;
    float s = 0.f;
    for (int t = 0; t < LBL; t++) s += x_dec[(b*LSEQ + t)*CIN + c];
    float m = s / (float)LBL;
    float v = 0.f;
    for (int t = 0; t < LBL; t++) {
        float d = x_dec[(b*LSEQ + t)*CIN + c] - m;
        v += d*d;
    }
    v /= (float)LBL;
    mean[i] = m;
    stdv[i] = sqrtf(v + EPSF);
}

// ---------------- token embed (circular conv k=3) + time features -----------
__global__ void embed_kernel(const float* __restrict__ x_dec,
                             const float* __restrict__ mark,
                             const float* __restrict__ token_w,  // (DM,CIN,3)
                             const float* __restrict__ timef_w,  // (DM,TFD)
                             const float* __restrict__ mean,
                             const float* __restrict__ stdv,
                             float* __restrict__ x) {
    int t = blockIdx.x, b = blockIdx.y;
    int m = threadIdx.x;
    __shared__ float xs[3][CIN];
    __shared__ float ms[TFD];
    if (threadIdx.x < 3*CIN) {
        int k = threadIdx.x / CIN, c = threadIdx.x % CIN;
        int s = (t - 1 + k + LSEQ) % LSEQ;
        float v = x_dec[(b*LSEQ + s)*CIN + c];
        if (s < LBL) v = (v - mean[b*CIN + c]) / stdv[b*CIN + c];
        xs[k][c] = v;
    }
    if (threadIdx.x >= 32 && threadIdx.x < 32 + TFD)
        ms[threadIdx.x - 32] = mark[(b*LSEQ + t)*TFD + threadIdx.x - 32];
    __syncthreads();
    float acc = 0.f;
    #pragma unroll
    for (int c = 0; c < CIN; c++)
        #pragma unroll
        for (int k = 0; k < 3; k++)
            acc += xs[k][c] * token_w[(m*CIN + c)*3 + k];
    #pragma unroll
    for (int f = 0; f < TFD; f++) acc += ms[f] * timef_w[m*TFD + f];
    x[((size_t)(b*LSEQ + t))*DM + m] = acc;
}

// --------------------------- layernorm (rows of DM) -------------------------
__global__ void ln_kernel(const float* __restrict__ x,
                          const float* __restrict__ w,
                          const float* __restrict__ bb,
                          float* __restrict__ out) {
    __shared__ float red[32];
    int row = blockIdx.x;
    const float* xr = x + (size_t)row*DM;
    int tid = threadIdx.x;
    float v0 = xr[tid], v1 = xr[tid + 256];
    float s = block_reduce_sum(v0 + v1, red);
    float m = s * (1.f/(float)DM);
    float d0 = v0 - m, d1 = v1 - m;
    float vs = block_reduce_sum(d0*d0 + d1*d1, red);
    float inv = rsqrtf(vs * (1.f/(float)DM) + EPSF);
    out[(size_t)row*DM + tid]       = d0*inv*w[tid]       + bb[tid];
    out[(size_t)row*DM + tid + 256] = d1*inv*w[tid + 256] + bb[tid + 256];
}

// ---------------------- TF32 tensor-core GEMM -------------------------------
// C[M,N] = A[M,K] @ W[N,K]^T.  MODE 0: store.  MODE 2: C += (residual).
// BM=BN=128, BK=32. 256 threads = 8 warps in 4(M)x2(N); warp tile 32x64.
template<int MODE>
__global__ void __launch_bounds__(256) gemm_tf32(const float* __restrict__ A, int lda,
                                                 const float* __restrict__ W,
                                                 float* __restrict__ C, int ldc,
                                                 int K) {
    __shared__ float As[128][36];
    __shared__ float Bs[128][36];
    const int tid = threadIdx.x;
    const int lane = tid & 31, warp = tid >> 5;
    const int wm = warp >> 1, wn = warp & 1;
    const int row0 = blockIdx.y * 128, col0 = blockIdx.x * 128;

    const int rA = tid >> 3;          // 0..31
    const int cA = (tid & 7) * 4;     // 0,4,..28

    float acc[2][8][4];
    #pragma unroll
    for (int i = 0; i < 2; i++)
        #pragma unroll
        for (int j = 0; j < 8; j++)
            #pragma unroll
            for (int q = 0; q < 4; q++) acc[i][j][q] = 0.f;

    float4 av[4], bv[4];
    const int KT = K >> 5;

    // prefetch tile 0
    #pragma unroll
    for (int i = 0; i < 4; i++) {
        int r = rA + 32*i;
        av[i] = *(const float4*)(A + (size_t)(row0 + r)*lda + cA);
        bv[i] = *(const float4*)(W + (size_t)(col0 + r)*K   + cA);
    }

    for (int kt = 0; kt < KT; kt++) {
        __syncthreads();
        #pragma unroll
        for (int i = 0; i < 4; i++) {
            int r = rA + 32*i;
            float4 ta, tb;
            ta.x = tf32r(av[i].x); ta.y = tf32r(av[i].y);
            ta.z = tf32r(av[i].z); ta.w = tf32r(av[i].w);
            tb.x = tf32r(bv[i].x); tb.y = tf32r(bv[i].y);
            tb.z = tf32r(bv[i].z); tb.w = tf32r(bv[i].w);
            *(float4*)&As[r][cA] = ta;
            *(float4*)&Bs[r][cA] = tb;
        }
        __syncthreads();
        if (kt + 1 < KT) {
            int k0 = (kt + 1) << 5;
            #pragma unroll
            for (int i = 0; i < 4; i++) {
                int r = rA + 32*i;
                av[i] = *(const float4*)(A + (size_t)(row0 + r)*lda + k0 + cA);
                bv[i] = *(const float4*)(W + (size_t)(col0 + r)*K   + k0 + cA);
            }
        }
        #pragma unroll
        for (int kk = 0; kk < 4; kk++) {
            const int kf = kk*8 + (lane & 3);
            unsigned int af[2][4];
            #pragma unroll
            for (int i = 0; i < 2; i++) {
                int r = wm*32 + i*16 + (lane >> 2);
                af[i][0] = __float_as_uint(As[r][kf]);
                af[i][1] = __float_as_uint(As[r+8][kf]);
                af[i][2] = __float_as_uint(As[r][kf+4]);
                af[i][3] = __float_as_uint(As[r+8][kf+4]);
            }
            #pragma unroll
            for (int j = 0; j < 8; j++) {
                int n = wn*64 + j*8 + (lane >> 2);
                unsigned int b0 = __float_as_uint(Bs[n][kf]);
                unsigned int b1 = __float_as_uint(Bs[n][kf+4]);
                #pragma unroll
                for (int i = 0; i < 2; i++) {
                    asm volatile(
                        "mma.sync.aligned.m16n8k8.row.col.f32.tf32.tf32.f32 "
                        "{%0,%1,%2,%3}, {%4,%5,%6,%7}, {%8,%9}, {%0,%1,%2,%3};"
                        : "+f"(acc[i][j][0]), "+f"(acc[i][j][1]),
                          "+f"(acc[i][j][2]), "+f"(acc[i][j][3])
                        : "r"(af[i][0]), "r"(af[i][1]), "r"(af[i][2]), "r"(af[i][3]),
                          "r"(b0), "r"(b1));
                }
            }
        }
    }

    // epilogue
    #pragma unroll
    for (int i = 0; i < 2; i++) {
        int gr = row0 + wm*32 + i*16 + (lane >> 2);
        #pragma unroll
        for (int j = 0; j < 8; j++) {
            int gc = col0 + wn*64 + j*8 + (lane & 3)*2;
            float* p0 = C + (size_t)gr*ldc + gc;
            float* p1 = C + (size_t)(gr + 8)*ldc + gc;
            if (MODE == 2) {
                p0[0] += acc[i][j][0]; p0[1] += acc[i][j][1];
                p1[0] += acc[i][j][2]; p1[1] += acc[i][j][3];
            } else {
                p0[0] = acc[i][j][0]; p0[1] = acc[i][j][1];
                p1[0] = acc[i][j][2]; p1[1] = acc[i][j][3];
            }
        }
    }
}

// ------------------------------ generic SGEMM (small GEMMs) ------------------
template<int BM, int BN, int BK, int TM, int TN>
__global__ void gemm_kernel(const float* __restrict__ A, int lda,
                            const float* __restrict__ W,
                            const float* __restrict__ bias,
                            float* __restrict__ C, int ldc,
                            int M, int Nn, int K, int mode) {
    constexpr int THREADS = (BM/TM)*(BN/TN);
    __shared__ float As[BK][BM];
    __shared__ float Bs[BK][BN];
    int tid = threadIdx.x;
    int tx = tid % (BN/TN);
    int ty = tid / (BN/TN);
    int row0 = blockIdx.y * BM;
    int col0 = blockIdx.x * BN;
    float acc[TM][TN];
    #pragma unroll
    for (int i = 0; i < TM; i++)
        #pragma unroll
        for (int j = 0; j < TN; j++) acc[i][j] = 0.f;

    for (int k0 = 0; k0 < K; k0 += BK) {
        #pragma unroll
        for (int i = tid; i < BM*BK; i += THREADS) {
            int m = i / BK, kk = i % BK;
            As[kk][m] = A[(size_t)(row0 + m)*lda + k0 + kk];
        }
        #pragma unroll
        for (int i = tid; i < BN*BK; i += THREADS) {
            int n = i / BK, kk = i % BK;
            Bs[kk][n] = W[(size_t)(col0 + n)*K + k0 + kk];
        }
        __syncthreads();
        #pragma unroll
        for (int kk = 0; kk < BK; kk++) {
            float a[TM], bfr[TN];
            #pragma unroll
            for (int i = 0; i < TM; i++) a[i] = As[kk][ty*TM + i];
            #pragma unroll
            for (int j = 0; j < TN; j++) bfr[j] = Bs[kk][tx*TN + j];
            #pragma unroll
            for (int i = 0; i < TM; i++)
                #pragma unroll
                for (int j = 0; j < TN; j++) acc[i][j] += a[i]*bfr[j];
        }
        __syncthreads();
    }
    #pragma unroll
    for (int i = 0; i < TM; i++) {
        int gm = row0 + ty*TM + i;
        #pragma unroll
        for (int j = 0; j < TN; j++) {
            int gn = col0 + tx*TN + j;
            float v = acc[i][j];
            if (mode == 1) {
                v += bias[gn];
                v = (v > 20.f) ? v : log1pf(expf(v));
            }
            if (mode == 2) C[(size_t)gm*ldc + gn] += v;
            else           C[(size_t)gm*ldc + gn]  = v;
        }
    }
}

// -------------------- depthwise causal conv (k=4) + SiLU --------------------
__global__ void dwconv_kernel(const float* __restrict__ xz,
                              const float* __restrict__ w,
                              const float* __restrict__ bias,
                              float* __restrict__ xc) {
    int gid = blockIdx.x * blockDim.x + threadIdx.x;
    int d = gid % DIN;
    int t = (gid / DIN) % LSEQ;
    int b = gid / (DIN * LSEQ);
    const float* xin = xz + (size_t)b * LSEQ * 2 * DIN;
    float acc = bias[d];
    #pragma unroll
    for (int k = 0; k < DCONV; k++) {
        int s = t - (DCONV-1) + k;
        if (s >= 0) acc += xin[(size_t)s*2*DIN + d] * w[d*DCONV + k];
    }
    xc[gid] = siluf(acc);
}

// --------------------------- selective scan ---------------------------------
__global__ void scan_kernel(const float* __restrict__ xc,
                            const float* __restrict__ dt,
                            const float* __restrict__ dbc,
                            const float* __restrict__ A_log,
                            const float* __restrict__ Dp,
                            const float* __restrict__ xz,
                            float* __restrict__ y) {
    int gid = blockIdx.x * blockDim.x + threadIdx.x;
    int n = gid & (NST - 1);
    int d = (gid >> 4) & (DIN - 1);
    int b = gid >> 14;
    float a  = -expf(A_log[d*NST + n]);
    float Dd = Dp[d];
    float h  = 0.f;
    const float* dbc_b = dbc + (size_t)b * LSEQ * 64;
    size_t base = (size_t)b * LSEQ * DIN + d;
    size_t zbase = (size_t)b * LSEQ * 2 * DIN + DIN + d;
    for (int t = 0; t < LSEQ; t++) {
        float dtv = dt[base + (size_t)t*DIN];
        float uv  = xc[base + (size_t)t*DIN];
        float Bv  = dbc_b[t*64 + DTR + n];
        float Cv  = dbc_b[t*64 + DTR + NST + n];
        float dA  = expf(dtv * a);
        h = dA*h + (dtv*uv)*Bv;
        float p = h * Cv;
        p += __shfl_xor_sync(0xffffffffu, p, 8);
        p += __shfl_xor_sync(0xffffffffu, p, 4);
        p += __shfl_xor_sync(0xffffffffu, p, 2);
        p += __shfl_xor_sync(0xffffffffu, p, 1);
        if (n == 0) {
            float zv = xz[zbase + (size_t)t*2*DIN];
            y[base + (size_t)t*DIN] = (p + uv*Dd) * siluf(zv);
        }
    }
}

// ------------------------- output head + denorm -----------------------------
__global__ void out_kernel(const float* __restrict__ xn,
                           const float* __restrict__ out_w,
                           const float* __restrict__ mean,
                           const float* __restrict__ stdv,
                           float* __restrict__ out) {
    int t_out = blockIdx.x, b = blockIdx.y;
    int t = LBL + t_out;
    __shared__ float row[DM];
    for (int i = threadIdx.x; i < DM; i += blockDim.x)
        row[i] = xn[((size_t)(b*LSEQ + t))*DM + i];
    __syncthreads();
    int c = threadIdx.x >> 5;
    int lane = threadIdx.x & 31;
    if (c < CIN) {
        float acc = 0.f;
        for (int i = lane; i < DM; i += 32) acc += row[i] * out_w[c*DM + i];
        #pragma unroll
        for (int o = 16; o; o >>= 1) acc += __shfl_xor_sync(0xffffffffu, acc, o);
        if (lane == 0)
            out[(size_t)(b*PRED + t_out)*CIN + c] = acc * stdv[b*CIN + c] + mean[b*CIN + c];
    }
}

// ------------------------------- launcher -----------------------------------
extern "C" void kernel_launch(void* const* d_in, const int* in_sizes, int n_in,
                              void* d_out, int out_size) {
    const float* x_dec    = (const float*)d_in[2];
    const float* mark     = (const float*)d_in[3];
    const float* token_w  = (const float*)d_in[4];
    const float* timef_w  = (const float*)d_in[5];
    const float* norm_w   = (const float*)d_in[6];
    const float* norm_b   = (const float*)d_in[7];
    const float* in_proj_w= (const float*)d_in[8];
    const float* conv_w   = (const float*)d_in[9];
    const float* conv_b   = (const float*)d_in[10];
    const float* xproj_w  = (const float*)d_in[11];
    const float* dtproj_w = (const float*)d_in[12];
    const float* dtproj_b = (const float*)d_in[13];
    const float* A_log    = (const float*)d_in[14];
    const float* Dp       = (const float*)d_in[15];
    const float* outproj_w= (const float*)d_in[16];
    const float* fin_w    = (const float*)d_in[17];
    const float* fin_b    = (const float*)d_in[18];
    const float* out_w    = (const float*)d_in[19];
    float* out = (float*)d_out;

    float *px, *pxn, *pxz, *pxc, *pdbc, *pdt, *py, *pmean, *pstd;
    cudaGetSymbolAddress((void**)&px,   g_x);
    cudaGetSymbolAddress((void**)&pxn,  g_xn);
    cudaGetSymbolAddress((void**)&pxz,  g_xz);
    cudaGetSymbolAddress((void**)&pxc,  g_xc);
    cudaGetSymbolAddress((void**)&pdbc, g_dbc);
    cudaGetSymbolAddress((void**)&pdt,  g_dt);
    cudaGetSymbolAddress((void**)&py,   g_y);
    cudaGetSymbolAddress((void**)&pmean,g_mean);
    cudaGetSymbolAddress((void**)&pstd, g_std);

    meanstd_kernel<<<1, 128>>>(x_dec, pmean, pstd);
    embed_kernel<<<dim3(LSEQ, BB), DM>>>(x_dec, mark, token_w, timef_w, pmean, pstd, px);

    for (int l = 0; l < NLAYER; l++) {
        ln_kernel<<<NTOK, 256>>>(px, norm_w + l*DM, norm_b + l*DM, pxn);
        // in_proj: (6144x512) @ (2048x512)^T -> (6144x2048)   [tensor cores]
        gemm_tf32<0><<<dim3(2*DIN/128, NTOK/128), 256>>>(
            pxn, DM, in_proj_w + (size_t)l*2*DIN*DM, pxz, 2*DIN, DM);
        dwconv_kernel<<<(NTOK*DIN)/256, 256>>>(pxz, conv_w + l*DIN*DCONV,
                                               conv_b + l*DIN, pxc);
        // x_proj: (6144x1024) @ (64x1024)^T -> (6144x64)
        gemm_kernel<64,64,16,4,4><<<dim3(1, NTOK/64), 256>>>(
            pxc, DIN, xproj_w + (size_t)l*64*DIN, nullptr, pdbc, 64,
            NTOK, 64, DIN, 0);
        // dt_proj: (6144x32) @ (1024x32)^T + bias, softplus -> (6144x1024)
        gemm_kernel<64,64,16,4,4><<<dim3(DIN/64, NTOK/64), 256>>>(
            pdbc, 64, dtproj_w + (size_t)l*DIN*DTR, dtproj_b + l*DIN, pdt, DIN,
            NTOK, DIN, DTR, 1);
        scan_kernel<<<(BB*DIN*NST)/256, 256>>>(pxc, pdt, pdbc,
                                               A_log + (size_t)l*DIN*NST,
                                               Dp + l*DIN, pxz, py);
        // out_proj (+residual): (6144x1024) @ (512x1024)^T -> += x  [tensor cores]
        gemm_tf32<2><<<dim3(DM/128, NTOK/128), 256>>>(
            py, DIN, outproj_w + (size_t)l*DM*DIN, px, DM, DIN);
    }

    ln_kernel<<<NTOK, 256>>>(px, fin_w, fin_b, pxn);
    out_kernel<<<dim3(PRED, BB), CIN*32>>>(pxn, out_w, pmean, pstd, out);
}

// round 6
// speedup vs baseline: 2.6178x; 1.3979x over previous
#include <cuda_runtime.h>
#include <stdint.h>
#include <math.h>

#define BB 16
#define LBL 48
#define PRED 336
#define LSEQ 384
#define CIN 7
#define TFD 4
#define DM 512
#define DIN 1024
#define NST 16
#define DTR 32
#define DCONV 4
#define NLAYER 2
#define EPSF 1e-5f

#define NTOK (BB*LSEQ)   // 6144 rows

// ------------------- scratch (static device globals; no allocs) -------------
__device__ float g_x  [NTOK*DM];
__device__ float g_xn [NTOK*DM];
__device__ float g_xz [NTOK*2*DIN];
__device__ float g_xc [NTOK*DIN];
__device__ float g_dbc[NTOK*64];
__device__ float g_dt [NTOK*DIN];
__device__ float g_y  [NTOK*DIN];
__device__ float g_mean[BB*CIN];
__device__ float g_std [BB*CIN];
__device__ float g_wi [NLAYER*2*DIN*DM];   // tf32-rounded in_proj weights
__device__ float g_wo [NLAYER*DM*DIN];     // tf32-rounded out_proj weights

// ------------------------------- helpers ------------------------------------
__device__ __forceinline__ float block_reduce_sum(float v, float* red) {
    __syncthreads();
    int lane = threadIdx.x & 31, wid = threadIdx.x >> 5;
    #pragma unroll
    for (int o = 16; o; o >>= 1) v += __shfl_xor_sync(0xffffffffu, v, o);
    if (lane == 0) red[wid] = v;
    __syncthreads();
    if (wid == 0) {
        float t = (lane < (int)(blockDim.x >> 5)) ? red[lane] : 0.f;
        #pragma unroll
        for (int o = 16; o; o >>= 1) t += __shfl_xor_sync(0xffffffffu, t, o);
        if (lane == 0) red[0] = t;
    }
    __syncthreads();
    return red[0];
}

__device__ __forceinline__ float silu_fast(float x) {
    return __fdividef(x, 1.f + __expf(-x));
}

__device__ __forceinline__ float tf32r(float x) {
    unsigned int u;
    asm("cvt.rna.tf32.f32 %0, %1;" : "=r"(u) : "f"(x));
    return __uint_as_float(u);
}

#define CP_ASYNC16(dst, src) \
    asm volatile("cp.async.cg.shared.global [%0], [%1], 16;" :: "r"(dst), "l"(src))

// --------------------- weight tf32 pre-rounding -----------------------------
__global__ void cvtw_kernel(const float* __restrict__ src, float* __restrict__ dst, int n) {
    int i = blockIdx.x * 256 + threadIdx.x;
    if (i < n) dst[i] = tf32r(src[i]);
}

// --------------------- mean/std over label window ---------------------------
__global__ void meanstd_kernel(const float* __restrict__ x_dec,
                               float* __restrict__ mean, float* __restrict__ stdv) {
    int i = threadIdx.x;
    if (i >= BB*CIN) return;
    int b = i / CIN, c = i % CIN;
    float s = 0.f;
    for (int t = 0; t < LBL; t++) s += x_dec[(b*LSEQ + t)*CIN + c];
    float m = s / (float)LBL;
    float v = 0.f;
    for (int t = 0; t < LBL; t++) {
        float d = x_dec[(b*LSEQ + t)*CIN + c] - m;
        v += d*d;
    }
    v /= (float)LBL;
    mean[i] = m;
    stdv[i] = sqrtf(v + EPSF);
}

// ---------------- token embed (circular conv k=3) + time features -----------
__global__ void embed_kernel(const float* __restrict__ x_dec,
                             const float* __restrict__ mark,
                             const float* __restrict__ token_w,
                             const float* __restrict__ timef_w,
                             const float* __restrict__ mean,
                             const float* __restrict__ stdv,
                             float* __restrict__ x) {
    int t = blockIdx.x, b = blockIdx.y;
    int m = threadIdx.x;
    __shared__ float xs[3][CIN];
    __shared__ float ms[TFD];
    if (threadIdx.x < 3*CIN) {
        int k = threadIdx.x / CIN, c = threadIdx.x % CIN;
        int s = (t - 1 + k + LSEQ) % LSEQ;
        float v = x_dec[(b*LSEQ + s)*CIN + c];
        if (s < LBL) v = (v - mean[b*CIN + c]) / stdv[b*CIN + c];
        xs[k][c] = v;
    }
    if (threadIdx.x >= 32 && threadIdx.x < 32 + TFD)
        ms[threadIdx.x - 32] = mark[(b*LSEQ + t)*TFD + threadIdx.x - 32];
    __syncthreads();
    float acc = 0.f;
    #pragma unroll
    for (int c = 0; c < CIN; c++)
        #pragma unroll
        for (int k = 0; k < 3; k++)
            acc += xs[k][c] * token_w[(m*CIN + c)*3 + k];
    #pragma unroll
    for (int f = 0; f < TFD; f++) acc += ms[f] * timef_w[m*TFD + f];
    x[((size_t)(b*LSEQ + t))*DM + m] = acc;
}

// --------------------------- layernorm (rows of DM) -------------------------
template<bool CVT>
__global__ void ln_kernel(const float* __restrict__ x,
                          const float* __restrict__ w,
                          const float* __restrict__ bb,
                          float* __restrict__ out) {
    __shared__ float red[32];
    int row = blockIdx.x;
    const float* xr = x + (size_t)row*DM;
    int tid = threadIdx.x;
    float v0 = xr[tid], v1 = xr[tid + 256];
    float s = block_reduce_sum(v0 + v1, red);
    float m = s * (1.f/(float)DM);
    float d0 = v0 - m, d1 = v1 - m;
    float vs = block_reduce_sum(d0*d0 + d1*d1, red);
    float inv = rsqrtf(vs * (1.f/(float)DM) + EPSF);
    float o0 = d0*inv*w[tid]       + bb[tid];
    float o1 = d1*inv*w[tid + 256] + bb[tid + 256];
    if (CVT) { o0 = tf32r(o0); o1 = tf32r(o1); }
    out[(size_t)row*DM + tid]       = o0;
    out[(size_t)row*DM + tid + 256] = o1;
}

// ---------------------- TF32 tensor-core GEMM, cp.async 3-stage --------------
// Inputs must already be tf32-rounded. C[M,N] = A[M,K] @ W[N,K]^T.
// MODE 0: store. MODE 2: C += (residual).
// BM=BN=128, BK=16, 3 stages, 256 threads (8 warps 4x2), warp tile 32x64.
#define SROW 20
#define TILE (128*SROW)
template<int MODE>
__global__ void __launch_bounds__(256, 2) gemm_tc(const float* __restrict__ A, int lda,
                                                  const float* __restrict__ W,
                                                  float* __restrict__ C, int ldc,
                                                  int K) {
    extern __shared__ float sm[];
    const int tid = threadIdx.x;
    const int lane = tid & 31, warp = tid >> 5;
    const int wm = warp >> 1, wn = warp & 1;
    const int row0 = blockIdx.y * 128, col0 = blockIdx.x * 128;
    const int KT = K >> 4;
    const unsigned sbase = (unsigned)__cvta_generic_to_shared(sm);

    float acc[2][8][4];
    #pragma unroll
    for (int i = 0; i < 2; i++)
        #pragma unroll
        for (int j = 0; j < 8; j++)
            #pragma unroll
            for (int q = 0; q < 4; q++) acc[i][j][q] = 0.f;

    // issue loads for k-tile kt into stage s
    #define ISSUE(kt_, s_) do {                                                 \
        int k0_ = (kt_) << 4;                                                   \
        _Pragma("unroll")                                                       \
        for (int h_ = 0; h_ < 2; h_++) {                                        \
            int c_ = tid + h_*256;                                              \
            int r_ = c_ >> 2, q_ = (c_ & 3) * 4;                                \
            const float* ga_ = A + (size_t)(row0 + r_)*lda + k0_ + q_;          \
            const float* gb_ = W + (size_t)(col0 + r_)*K   + k0_ + q_;          \
            unsigned da_ = sbase + (unsigned)(((s_)*2*TILE + r_*SROW + q_)*4);  \
            unsigned db_ = sbase + (unsigned)(((s_)*2*TILE + TILE + r_*SROW + q_)*4); \
            CP_ASYNC16(da_, ga_);                                               \
            CP_ASYNC16(db_, gb_);                                               \
        }                                                                       \
        asm volatile("cp.async.commit_group;");                                 \
    } while (0)

    ISSUE(0, 0);
    ISSUE(1, 1);

    for (int kt = 0; kt < KT; kt++) {
        if (kt + 2 < KT) asm volatile("cp.async.wait_group 1;");
        else             asm volatile("cp.async.wait_group 0;");
        __syncthreads();
        if (kt + 2 < KT) ISSUE(kt + 2, (kt + 2) % 3);

        const float* As_ = sm + (kt % 3) * 2 * TILE;
        const float* Bs_ = As_ + TILE;

        #pragma unroll
        for (int kk = 0; kk < 2; kk++) {
            const int kf = kk*8 + (lane & 3);
            unsigned int af[2][4];
            #pragma unroll
            for (int i = 0; i < 2; i++) {
                int r = wm*32 + i*16 + (lane >> 2);
                af[i][0] = __float_as_uint(As_[r*SROW + kf]);
                af[i][1] = __float_as_uint(As_[(r+8)*SROW + kf]);
                af[i][2] = __float_as_uint(As_[r*SROW + kf + 4]);
                af[i][3] = __float_as_uint(As_[(r+8)*SROW + kf + 4]);
            }
            #pragma unroll
            for (int j = 0; j < 8; j++) {
                int n = wn*64 + j*8 + (lane >> 2);
                unsigned int b0 = __float_as_uint(Bs_[n*SROW + kf]);
                unsigned int b1 = __float_as_uint(Bs_[n*SROW + kf + 4]);
                #pragma unroll
                for (int i = 0; i < 2; i++) {
                    asm volatile(
                        "mma.sync.aligned.m16n8k8.row.col.f32.tf32.tf32.f32 "
                        "{%0,%1,%2,%3}, {%4,%5,%6,%7}, {%8,%9}, {%0,%1,%2,%3};"
                        : "+f"(acc[i][j][0]), "+f"(acc[i][j][1]),
                          "+f"(acc[i][j][2]), "+f"(acc[i][j][3])
                        : "r"(af[i][0]), "r"(af[i][1]), "r"(af[i][2]), "r"(af[i][3]),
                          "r"(b0), "r"(b1));
                }
            }
        }
    }
    #undef ISSUE

    #pragma unroll
    for (int i = 0; i < 2; i++) {
        int gr = row0 + wm*32 + i*16 + (lane >> 2);
        #pragma unroll
        for (int j = 0; j < 8; j++) {
            int gc = col0 + wn*64 + j*8 + (lane & 3)*2;
            float* p0 = C + (size_t)gr*ldc + gc;
            float* p1 = C + (size_t)(gr + 8)*ldc + gc;
            if (MODE == 2) {
                p0[0] += acc[i][j][0]; p0[1] += acc[i][j][1];
                p1[0] += acc[i][j][2]; p1[1] += acc[i][j][3];
            } else {
                p0[0] = acc[i][j][0]; p0[1] = acc[i][j][1];
                p1[0] = acc[i][j][2]; p1[1] = acc[i][j][3];
            }
        }
    }
}

// ------------------------------ SIMT GEMM (small GEMMs) ----------------------
// k-range per block: [blockIdx.z*KC, blockIdx.z*KC + KC)
// mode 1: softplus(v+bias) store.  mode 3: atomicAdd.
template<int BM, int BN, int BK, int TM, int TN>
__global__ void gemm_kernel(const float* __restrict__ A, int lda,
                            const float* __restrict__ W,
                            const float* __restrict__ bias,
                            float* __restrict__ C, int ldc,
                            int M, int Nn, int K, int KC, int mode) {
    constexpr int THREADS = (BM/TM)*(BN/TN);
    __shared__ float As[BK][BM];
    __shared__ float Bs[BK][BN];
    int tid = threadIdx.x;
    int tx = tid % (BN/TN);
    int ty = tid / (BN/TN);
    int row0 = blockIdx.y * BM;
    int col0 = blockIdx.x * BN;
    int kbeg = blockIdx.z * KC;
    float acc[TM][TN];
    #pragma unroll
    for (int i = 0; i < TM; i++)
        #pragma unroll
        for (int j = 0; j < TN; j++) acc[i][j] = 0.f;

    for (int k0 = kbeg; k0 < kbeg + KC; k0 += BK) {
        #pragma unroll
        for (int i = tid; i < BM*BK; i += THREADS) {
            int m = i / BK, kk = i % BK;
            As[kk][m] = A[(size_t)(row0 + m)*lda + k0 + kk];
        }
        #pragma unroll
        for (int i = tid; i < BN*BK; i += THREADS) {
            int n = i / BK, kk = i % BK;
            Bs[kk][n] = W[(size_t)(col0 + n)*K + k0 + kk];
        }
        __syncthreads();
        #pragma unroll
        for (int kk = 0; kk < BK; kk++) {
            float a[TM], bfr[TN];
            #pragma unroll
            for (int i = 0; i < TM; i++) a[i] = As[kk][ty*TM + i];
            #pragma unroll
            for (int j = 0; j < TN; j++) bfr[j] = Bs[kk][tx*TN + j];
            #pragma unroll
            for (int i = 0; i < TM; i++)
                #pragma unroll
                for (int j = 0; j < TN; j++) acc[i][j] += a[i]*bfr[j];
        }
        __syncthreads();
    }
    #pragma unroll
    for (int i = 0; i < TM; i++) {
        int gm = row0 + ty*TM + i;
        #pragma unroll
        for (int j = 0; j < TN; j++) {
            int gn = col0 + tx*TN + j;
            float v = acc[i][j];
            if (mode == 1) {
                v += bias[gn];
                v = (v > 20.f) ? v : __logf(1.f + __expf(v));
            }
            if (mode == 3)      atomicAdd(&C[(size_t)gm*ldc + gn], v);
            else                C[(size_t)gm*ldc + gn] = v;
        }
    }
}

// -------------------- depthwise causal conv (k=4) + SiLU --------------------
__global__ void dwconv_kernel(const float* __restrict__ xz,
                              const float* __restrict__ w,
                              const float* __restrict__ bias,
                              float* __restrict__ xc) {
    int gid = blockIdx.x * blockDim.x + threadIdx.x;
    int d = gid % DIN;
    int t = (gid / DIN) % LSEQ;
    int b = gid / (DIN * LSEQ);
    const float* xin = xz + (size_t)b * LSEQ * 2 * DIN;
    float acc = bias[d];
    #pragma unroll
    for (int k = 0; k < DCONV; k++) {
        int s = t - (DCONV-1) + k;
        if (s >= 0) acc += xin[(size_t)s*2*DIN + d] * w[d*DCONV + k];
    }
    xc[gid] = silu_fast(acc);
}

// --------------------------- selective scan ---------------------------------
__global__ void scan_kernel(const float* __restrict__ xc,
                            const float* __restrict__ dt,
                            const float* __restrict__ dbc,
                            const float* __restrict__ A_log,
                            const float* __restrict__ Dp,
                            const float* __restrict__ xz,
                            float* __restrict__ y) {
    int gid = blockIdx.x * blockDim.x + threadIdx.x;
    int n = gid & (NST - 1);
    int d = (gid >> 4) & (DIN - 1);
    int b = gid >> 14;
    float a  = -__expf(A_log[d*NST + n]);
    float Dd = Dp[d];
    float h  = 0.f;
    const float* dbc_b = dbc + (size_t)b * LSEQ * 64;
    size_t base = (size_t)b * LSEQ * DIN + d;
    size_t zbase = (size_t)b * LSEQ * 2 * DIN + DIN + d;
    for (int t = 0; t < LSEQ; t++) {
        float dtv = dt[base + (size_t)t*DIN];
        float uv  = xc[base + (size_t)t*DIN];
        float Bv  = dbc_b[t*64 + DTR + n];
        float Cv  = dbc_b[t*64 + DTR + NST + n];
        float dA  = __expf(dtv * a);
        h = dA*h + (dtv*uv)*Bv;
        float p = h * Cv;
        p += __shfl_xor_sync(0xffffffffu, p, 8);
        p += __shfl_xor_sync(0xffffffffu, p, 4);
        p += __shfl_xor_sync(0xffffffffu, p, 2);
        p += __shfl_xor_sync(0xffffffffu, p, 1);
        if (n == 0) {
            float zv = xz[zbase + (size_t)t*2*DIN];
            y[base + (size_t)t*DIN] = tf32r((p + uv*Dd) * silu_fast(zv));
        }
    }
}

// ------------------------- output head + denorm -----------------------------
__global__ void out_kernel(const float* __restrict__ xn,
                           const float* __restrict__ out_w,
                           const float* __restrict__ mean,
                           const float* __restrict__ stdv,
                           float* __restrict__ out) {
    int t_out = blockIdx.x, b = blockIdx.y;
    int t = LBL + t_out;
    __shared__ float row[DM];
    for (int i = threadIdx.x; i < DM; i += blockDim.x)
        row[i] = xn[((size_t)(b*LSEQ + t))*DM + i];
    __syncthreads();
    int c = threadIdx.x >> 5;
    int lane = threadIdx.x & 31;
    if (c < CIN) {
        float acc = 0.f;
        for (int i = lane; i < DM; i += 32) acc += row[i] * out_w[c*DM + i];
        #pragma unroll
        for (int o = 16; o; o >>= 1) acc += __shfl_xor_sync(0xffffffffu, acc, o);
        if (lane == 0)
            out[(size_t)(b*PRED + t_out)*CIN + c] = acc * stdv[b*CIN + c] + mean[b*CIN + c];
    }
}

// ------------------------------- launcher -----------------------------------
extern "C" void kernel_launch(void* const* d_in, const int* in_sizes, int n_in,
                              void* d_out, int out_size) {
    const float* x_dec    = (const float*)d_in[2];
    const float* mark     = (const float*)d_in[3];
    const float* token_w  = (const float*)d_in[4];
    const float* timef_w  = (const float*)d_in[5];
    const float* norm_w   = (const float*)d_in[6];
    const float* norm_b   = (const float*)d_in[7];
    const float* in_proj_w= (const float*)d_in[8];
    const float* conv_w   = (const float*)d_in[9];
    const float* conv_b   = (const float*)d_in[10];
    const float* xproj_w  = (const float*)d_in[11];
    const float* dtproj_w = (const float*)d_in[12];
    const float* dtproj_b = (const float*)d_in[13];
    const float* A_log    = (const float*)d_in[14];
    const float* Dp       = (const float*)d_in[15];
    const float* outproj_w= (const float*)d_in[16];
    const float* fin_w    = (const float*)d_in[17];
    const float* fin_b    = (const float*)d_in[18];
    const float* out_w    = (const float*)d_in[19];
    float* out = (float*)d_out;

    float *px, *pxn, *pxz, *pxc, *pdbc, *pdt, *py, *pmean, *pstd, *pwi, *pwo;
    cudaGetSymbolAddress((void**)&px,   g_x);
    cudaGetSymbolAddress((void**)&pxn,  g_xn);
    cudaGetSymbolAddress((void**)&pxz,  g_xz);
    cudaGetSymbolAddress((void**)&pxc,  g_xc);
    cudaGetSymbolAddress((void**)&pdbc, g_dbc);
    cudaGetSymbolAddress((void**)&pdt,  g_dt);
    cudaGetSymbolAddress((void**)&py,   g_y);
    cudaGetSymbolAddress((void**)&pmean,g_mean);
    cudaGetSymbolAddress((void**)&pstd, g_std);
    cudaGetSymbolAddress((void**)&pwi,  g_wi);
    cudaGetSymbolAddress((void**)&pwo,  g_wo);

    const int SMEM_TC = 3*2*TILE*4;   // 61440 bytes
    cudaFuncSetAttribute(gemm_tc<0>, cudaFuncAttributeMaxDynamicSharedMemorySize, SMEM_TC);
    cudaFuncSetAttribute(gemm_tc<2>, cudaFuncAttributeMaxDynamicSharedMemorySize, SMEM_TC);

    // pre-round weights to tf32 (rna) once
    {
        int ni = NLAYER*2*DIN*DM, no = NLAYER*DM*DIN;
        cvtw_kernel<<<(ni + 255)/256, 256>>>(in_proj_w, pwi, ni);
        cvtw_kernel<<<(no + 255)/256, 256>>>(outproj_w, pwo, no);
    }

    meanstd_kernel<<<1, 128>>>(x_dec, pmean, pstd);
    embed_kernel<<<dim3(LSEQ, BB), DM>>>(x_dec, mark, token_w, timef_w, pmean, pstd, px);

    for (int l = 0; l < NLAYER; l++) {
        ln_kernel<true><<<NTOK, 256>>>(px, norm_w + l*DM, norm_b + l*DM, pxn);
        // in_proj: (6144x512) @ (2048x512)^T -> (6144x2048)
        gemm_tc<0><<<dim3(2*DIN/128, NTOK/128), 256, SMEM_TC>>>(
            pxn, DM, pwi + (size_t)l*2*DIN*DM, pxz, 2*DIN, DM);
        dwconv_kernel<<<(NTOK*DIN)/256, 256>>>(pxz, conv_w + l*DIN*DCONV,
                                               conv_b + l*DIN, pxc);
        // x_proj: (6144x1024) @ (64x1024)^T -> (6144x64), split-K x4
        cudaMemsetAsync(pdbc, 0, (size_t)NTOK*64*sizeof(float));
        gemm_kernel<64,64,16,4,4><<<dim3(1, NTOK/64, 4), 256>>>(
            pxc, DIN, xproj_w + (size_t)l*64*DIN, nullptr, pdbc, 64,
            NTOK, 64, DIN, DIN/4, 3);
        // dt_proj: (6144x32) @ (1024x32)^T + bias, softplus -> (6144x1024)
        gemm_kernel<64,64,16,4,4><<<dim3(DIN/64, NTOK/64, 1), 256>>>(
            pdbc, 64, dtproj_w + (size_t)l*DIN*DTR, dtproj_b + l*DIN, pdt, DIN,
            NTOK, DIN, DTR, DTR, 1);
        scan_kernel<<<(BB*DIN*NST)/256, 256>>>(pxc, pdt, pdbc,
                                               A_log + (size_t)l*DIN*NST,
                                               Dp + l*DIN, pxz, py);
        // out_proj (+residual): (6144x1024) @ (512x1024)^T -> += x
        gemm_tc<2><<<dim3(DM/128, NTOK/128), 256, SMEM_TC>>>(
            py, DIN, pwo + (size_t)l*DM*DIN, px, DM, DIN);
    }

    ln_kernel<false><<<NTOK, 256>>>(px, fin_w, fin_b, pxn);
    out_kernel<<<dim3(PRED, BB), CIN*32>>>(pxn, out_w, pmean, pstd, out);
}

// round 8
// speedup vs baseline: 2.6185x; 1.0003x over previous
#include <cuda_runtime.h>
#include <stdint.h>
#include <math.h>

#define BB 16
#define LBL 48
#define PRED 336
#define LSEQ 384
#define CIN 7
#define TFD 4
#define DM 512
#define DIN 1024
#define NST 16
#define DTR 32
#define DCONV 4
#define NLAYER 2
#define EPSF 1e-5f

#define NTOK (BB*LSEQ)   // 6144 rows
#define KEMB 28

// ------------------- scratch (static device globals; no allocs) -------------
__device__ float g_x  [NTOK*DM];
__device__ float g_xn [NTOK*DM];
__device__ float g_xz [NTOK*2*DIN];
__device__ float g_xc [NTOK*DIN];
__device__ float g_dbc[NTOK*64];
__device__ float g_y  [NTOK*DIN];
__device__ float g_mean[BB*CIN];
__device__ float g_std [BB*CIN];
__device__ float g_wi [NLAYER*2*DIN*DM];   // tf32-rounded in_proj weights
__device__ float g_wo [NLAYER*DM*DIN];     // tf32-rounded out_proj weights
__device__ float g_a28[NTOK*KEMB];         // embed input windows
__device__ float g_w28[DM*KEMB];           // embed packed weights

// ------------------------------- helpers ------------------------------------
__device__ __forceinline__ float block_reduce_sum(float v, float* red) {
    __syncthreads();
    int lane = threadIdx.x & 31, wid = threadIdx.x >> 5;
    #pragma unroll
    for (int o = 16; o; o >>= 1) v += __shfl_xor_sync(0xffffffffu, v, o);
    if (lane == 0) red[wid] = v;
    __syncthreads();
    if (wid == 0) {
        float t = (lane < (int)(blockDim.x >> 5)) ? red[lane] : 0.f;
        #pragma unroll
        for (int o = 16; o; o >>= 1) t += __shfl_xor_sync(0xffffffffu, t, o);
        if (lane == 0) red[0] = t;
    }
    __syncthreads();
    return red[0];
}

__device__ __forceinline__ float silu_fast(float x) {
    return __fdividef(x, 1.f + __expf(-x));
}

__device__ __forceinline__ float tf32r(float x) {
    unsigned int u;
    asm("cvt.rna.tf32.f32 %0, %1;" : "=r"(u) : "f"(x));
    return __uint_as_float(u);
}

#define CP_ASYNC16(dst, src) \
    asm volatile("cp.async.cg.shared.global [%0], [%1], 16;" :: "r"(dst), "l"(src))

// --------------------- weight tf32 pre-rounding -----------------------------
__global__ void cvtw_kernel(const float* __restrict__ src, float* __restrict__ dst, int n) {
    int i = blockIdx.x * 256 + threadIdx.x;
    if (i < n) dst[i] = tf32r(src[i]);
}

// --------------------- mean/std over label window ---------------------------
__global__ void meanstd_kernel(const float* __restrict__ x_dec,
                               float* __restrict__ mean, float* __restrict__ stdv) {
    int i = threadIdx.x;
    if (i >= BB*CIN) return;
    int b = i / CIN, c = i % CIN;
    float s = 0.f;
    for (int t = 0; t < LBL; t++) s += x_dec[(b*LSEQ + t)*CIN + c];
    float m = s / (float)LBL;
    float v = 0.f;
    for (int t = 0; t < LBL; t++) {
        float d = x_dec[(b*LSEQ + t)*CIN + c] - m;
        v += d*d;
    }
    v /= (float)LBL;
    mean[i] = m;
    stdv[i] = sqrtf(v + EPSF);
}

// ---------------- embed prep: window matrix + packed weights -----------------
__global__ void embed_prep(const float* __restrict__ x_dec,
                           const float* __restrict__ mark,
                           const float* __restrict__ mean,
                           const float* __restrict__ stdv,
                           float* __restrict__ A28) {
    int i = blockIdx.x * 256 + threadIdx.x;
    if (i >= NTOK*KEMB) return;
    int col = i % KEMB, tok = i / KEMB;
    int b = tok / LSEQ, t = tok % LSEQ;
    float v = 0.f;
    if (col < 21) {
        int c = col / 3, k = col % 3;
        int s = (t - 1 + k + LSEQ) % LSEQ;
        v = x_dec[(b*LSEQ + s)*CIN + c];
        if (s < LBL) v = (v - mean[b*CIN + c]) / stdv[b*CIN + c];
    } else if (col < 25) {
        v = mark[(b*LSEQ + t)*TFD + col - 21];
    }
    A28[i] = v;
}

__global__ void w28_prep(const float* __restrict__ token_w,
                         const float* __restrict__ timef_w,
                         float* __restrict__ W28) {
    int i = blockIdx.x * 256 + threadIdx.x;
    if (i >= DM*KEMB) return;
    int m = i / KEMB, j = i % KEMB;
    float v = 0.f;
    if (j < 21)      v = token_w[m*21 + j];
    else if (j < 25) v = timef_w[m*TFD + j - 21];
    W28[i] = v;
}

// --------------------------- layernorm (rows of DM) -------------------------
template<bool CVT>
__global__ void ln_kernel(const float* __restrict__ x,
                          const float* __restrict__ w,
                          const float* __restrict__ bb,
                          float* __restrict__ out) {
    __shared__ float red[32];
    int row = blockIdx.x;
    const float* xr = x + (size_t)row*DM;
    int tid = threadIdx.x;
    float v0 = xr[tid], v1 = xr[tid + 256];
    float s = block_reduce_sum(v0 + v1, red);
    float m = s * (1.f/(float)DM);
    float d0 = v0 - m, d1 = v1 - m;
    float vs = block_reduce_sum(d0*d0 + d1*d1, red);
    float inv = rsqrtf(vs * (1.f/(float)DM) + EPSF);
    float o0 = d0*inv*w[tid]       + bb[tid];
    float o1 = d1*inv*w[tid + 256] + bb[tid + 256];
    if (CVT) { o0 = tf32r(o0); o1 = tf32r(o1); }
    out[(size_t)row*DM + tid]       = o0;
    out[(size_t)row*DM + tid + 256] = o1;
}

// ---------------------- TF32 tensor-core GEMM, cp.async 3-stage --------------
#define SROW 20
#define TILE (128*SROW)
template<int MODE>
__global__ void __launch_bounds__(256, 2) gemm_tc(const float* __restrict__ A, int lda,
                                                  const float* __restrict__ W,
                                                  float* __restrict__ C, int ldc,
                                                  int K) {
    extern __shared__ float sm[];
    const int tid = threadIdx.x;
    const int lane = tid & 31, warp = tid >> 5;
    const int wm = warp >> 1, wn = warp & 1;
    const int row0 = blockIdx.y * 128, col0 = blockIdx.x * 128;
    const int KT = K >> 4;
    const unsigned sbase = (unsigned)__cvta_generic_to_shared(sm);

    float acc[2][8][4];
    #pragma unroll
    for (int i = 0; i < 2; i++)
        #pragma unroll
        for (int j = 0; j < 8; j++)
            #pragma unroll
            for (int q = 0; q < 4; q++) acc[i][j][q] = 0.f;

    #define ISSUE(kt_, s_) do {                                                 \
        int k0_ = (kt_) << 4;                                                   \
        _Pragma("unroll")                                                       \
        for (int h_ = 0; h_ < 2; h_++) {                                        \
            int c_ = tid + h_*256;                                              \
            int r_ = c_ >> 2, q_ = (c_ & 3) * 4;                                \
            const float* ga_ = A + (size_t)(row0 + r_)*lda + k0_ + q_;          \
            const float* gb_ = W + (size_t)(col0 + r_)*K   + k0_ + q_;          \
            unsigned da_ = sbase + (unsigned)(((s_)*2*TILE + r_*SROW + q_)*4);  \
            unsigned db_ = sbase + (unsigned)(((s_)*2*TILE + TILE + r_*SROW + q_)*4); \
            CP_ASYNC16(da_, ga_);                                               \
            CP_ASYNC16(db_, gb_);                                               \
        }                                                                       \
        asm volatile("cp.async.commit_group;");                                 \
    } while (0)

    ISSUE(0, 0);
    ISSUE(1, 1);

    for (int kt = 0; kt < KT; kt++) {
        if (kt + 2 < KT) asm volatile("cp.async.wait_group 1;");
        else             asm volatile("cp.async.wait_group 0;");
        __syncthreads();
        if (kt + 2 < KT) ISSUE(kt + 2, (kt + 2) % 3);

        const float* As_ = sm + (kt % 3) * 2 * TILE;
        const float* Bs_ = As_ + TILE;

        #pragma unroll
        for (int kk = 0; kk < 2; kk++) {
            const int kf = kk*8 + (lane & 3);
            unsigned int af[2][4];
            #pragma unroll
            for (int i = 0; i < 2; i++) {
                int r = wm*32 + i*16 + (lane >> 2);
                af[i][0] = __float_as_uint(As_[r*SROW + kf]);
                af[i][1] = __float_as_uint(As_[(r+8)*SROW + kf]);
                af[i][2] = __float_as_uint(As_[r*SROW + kf + 4]);
                af[i][3] = __float_as_uint(As_[(r+8)*SROW + kf + 4]);
            }
            #pragma unroll
            for (int j = 0; j < 8; j++) {
                int n = wn*64 + j*8 + (lane >> 2);
                unsigned int b0 = __float_as_uint(Bs_[n*SROW + kf]);
                unsigned int b1 = __float_as_uint(Bs_[n*SROW + kf + 4]);
                #pragma unroll
                for (int i = 0; i < 2; i++) {
                    asm volatile(
                        "mma.sync.aligned.m16n8k8.row.col.f32.tf32.tf32.f32 "
                        "{%0,%1,%2,%3}, {%4,%5,%6,%7}, {%8,%9}, {%0,%1,%2,%3};"
                        : "+f"(acc[i][j][0]), "+f"(acc[i][j][1]),
                          "+f"(acc[i][j][2]), "+f"(acc[i][j][3])
                        : "r"(af[i][0]), "r"(af[i][1]), "r"(af[i][2]), "r"(af[i][3]),
                          "r"(b0), "r"(b1));
                }
            }
        }
    }
    #undef ISSUE

    #pragma unroll
    for (int i = 0; i < 2; i++) {
        int gr = row0 + wm*32 + i*16 + (lane >> 2);
        #pragma unroll
        for (int j = 0; j < 8; j++) {
            int gc = col0 + wn*64 + j*8 + (lane & 3)*2;
            float* p0 = C + (size_t)gr*ldc + gc;
            float* p1 = C + (size_t)(gr + 8)*ldc + gc;
            if (MODE == 2) {
                p0[0] += acc[i][j][0]; p0[1] += acc[i][j][1];
                p1[0] += acc[i][j][2]; p1[1] += acc[i][j][3];
            } else {
                p0[0] = acc[i][j][0]; p0[1] = acc[i][j][1];
                p1[0] = acc[i][j][2]; p1[1] = acc[i][j][3];
            }
        }
    }
}

// ------------------------------ SIMT GEMM ------------------------------------
// mode 0: store.  mode 3: atomicAdd (split-K).
template<int BM, int BN, int BK, int TM, int TN>
__global__ void gemm_kernel(const float* __restrict__ A, int lda,
                            const float* __restrict__ W,
                            const float* __restrict__ bias,
                            float* __restrict__ C, int ldc,
                            int M, int Nn, int K, int KC, int mode) {
    constexpr int THREADS = (BM/TM)*(BN/TN);
    __shared__ float As[BK][BM];
    __shared__ float Bs[BK][BN];
    int tid = threadIdx.x;
    int tx = tid % (BN/TN);
    int ty = tid / (BN/TN);
    int row0 = blockIdx.y * BM;
    int col0 = blockIdx.x * BN;
    int kbeg = blockIdx.z * KC;
    float acc[TM][TN];
    #pragma unroll
    for (int i = 0; i < TM; i++)
        #pragma unroll
        for (int j = 0; j < TN; j++) acc[i][j] = 0.f;

    for (int k0 = kbeg; k0 < kbeg + KC; k0 += BK) {
        #pragma unroll
        for (int i = tid; i < BM*BK; i += THREADS) {
            int m = i / BK, kk = i % BK;
            As[kk][m] = A[(size_t)(row0 + m)*lda + k0 + kk];
        }
        #pragma unroll
        for (int i = tid; i < BN*BK; i += THREADS) {
            int n = i / BK, kk = i % BK;
            Bs[kk][n] = W[(size_t)(col0 + n)*K + k0 + kk];
        }
        __syncthreads();
        #pragma unroll
        for (int kk = 0; kk < BK; kk++) {
            float a[TM], bfr[TN];
            #pragma unroll
            for (int i = 0; i < TM; i++) a[i] = As[kk][ty*TM + i];
            #pragma unroll
            for (int j = 0; j < TN; j++) bfr[j] = Bs[kk][tx*TN + j];
            #pragma unroll
            for (int i = 0; i < TM; i++)
                #pragma unroll
                for (int j = 0; j < TN; j++) acc[i][j] += a[i]*bfr[j];
        }
        __syncthreads();
    }
    #pragma unroll
    for (int i = 0; i < TM; i++) {
        int gm = row0 + ty*TM + i;
        #pragma unroll
        for (int j = 0; j < TN; j++) {
            int gn = col0 + tx*TN + j;
            float v = acc[i][j];
            if (mode == 3)      atomicAdd(&C[(size_t)gm*ldc + gn], v);
            else                C[(size_t)gm*ldc + gn] = v;
        }
    }
}

// -------------------- depthwise causal conv (k=4) + SiLU --------------------
__global__ void dwconv_kernel(const float* __restrict__ xz,
                              const float* __restrict__ w,
                              const float* __restrict__ bias,
                              float* __restrict__ xc) {
    int gid = blockIdx.x * blockDim.x + threadIdx.x;
    int d = gid % DIN;
    int t = (gid / DIN) % LSEQ;
    int b = gid / (DIN * LSEQ);
    const float* xin = xz + (size_t)b * LSEQ * 2 * DIN;
    float acc = bias[d];
    #pragma unroll
    for (int k = 0; k < DCONV; k++) {
        int s = t - (DCONV-1) + k;
        if (s >= 0) acc += xin[(size_t)s*2*DIN + d] * w[d*DCONV + k];
    }
    xc[gid] = silu_fast(acc);
}

// --------------- fused dt_proj + softplus + selective scan ------------------
// thread = (b, d): 16 n-states in registers. dbc chunk staged in smem.
// dA_n = exp(dt*a_n); when a_n = (n+1)*a_0 (A_log = log(1..N)) use powers of
// e1 = exp(dt*a_0) — 1 exp/step instead of 16. Fallback handles general A.
#define TCH 48
__global__ void __launch_bounds__(128) dtscan_kernel(
    const float* __restrict__ xc,
    const float* __restrict__ dbc,
    const float* __restrict__ dtw,   // (DIN, DTR)
    const float* __restrict__ dtb,   // (DIN)
    const float* __restrict__ A_log, // (DIN, NST)
    const float* __restrict__ Dp,    // (DIN)
    const float* __restrict__ xz,    // z at +DIN
    float* __restrict__ y) {
    __shared__ float sdbc[TCH][64];
    int b = blockIdx.x;
    int d = blockIdx.y * 128 + threadIdx.x;
    float h[NST], a[NST], w[DTR];
    #pragma unroll
    for (int n = 0; n < NST; n++) {
        h[n] = 0.f;
        a[n] = -__expf(A_log[d*NST + n]);
    }
    #pragma unroll
    for (int j = 0; j < DTR; j++) w[j] = dtw[d*DTR + j];
    float bias = dtb[d], Dd = Dp[d];
    bool geom = true;
    #pragma unroll
    for (int n = 1; n < NST; n++) {
        float pred = (float)(n+1) * a[0];
        if (fabsf(a[n] - pred) > 1e-4f * fmaxf(1.f, fabsf(a[n]))) geom = false;
    }
    const float* dbc_b = dbc + (size_t)b * LSEQ * 64;
    size_t base = (size_t)b * LSEQ * DIN + d;
    size_t zb   = (size_t)b * LSEQ * 2 * DIN + DIN + d;

    for (int t0 = 0; t0 < LSEQ; t0 += TCH) {
        __syncthreads();
        #pragma unroll
        for (int i = 0; i < (TCH*64)/(128*4); i++) {
            int idx = threadIdx.x + i*128;
            ((float4*)&sdbc[0][0])[idx] = ((const float4*)(dbc_b + t0*64))[idx];
        }
        __syncthreads();
        for (int tt = 0; tt < TCH; tt++) {
            int t = t0 + tt;
            float u = xc[base + (size_t)t*DIN];
            float z = xz[zb + (size_t)t*2*DIN];
            // dt_proj: dot(w, dt_r) + bias, two partial sums for ILP
            float v0 = bias, v1 = 0.f;
            const float4* dr = (const float4*)&sdbc[tt][0];
            #pragma unroll
            for (int j = 0; j < 4; j++) {
                float4 q0 = dr[2*j], q1 = dr[2*j+1];
                v0 += w[8*j+0]*q0.x + w[8*j+1]*q0.y + w[8*j+2]*q0.z + w[8*j+3]*q0.w;
                v1 += w[8*j+4]*q1.x + w[8*j+5]*q1.y + w[8*j+6]*q1.z + w[8*j+7]*q1.w;
            }
            float v = v0 + v1;
            float dt = (v > 20.f) ? v : __logf(1.f + __expf(v));
            float du = dt * u;
            const float4* Bv = (const float4*)&sdbc[tt][DTR];
            const float4* Cv = (const float4*)&sdbc[tt][DTR + NST];
            float acc0 = 0.f, acc1 = 0.f;
            if (geom) {
                float e1 = __expf(dt * a[0]);
                float dA = e1;
                #pragma unroll
                for (int q = 0; q < 4; q++) {
                    float4 Bq = Bv[q], Cq = Cv[q];
                    h[4*q+0] = dA*h[4*q+0] + du*Bq.x; acc0 += h[4*q+0]*Cq.x; dA *= e1;
                    h[4*q+1] = dA*h[4*q+1] + du*Bq.y; acc1 += h[4*q+1]*Cq.y; dA *= e1;
                    h[4*q+2] = dA*h[4*q+2] + du*Bq.z; acc0 += h[4*q+2]*Cq.z; dA *= e1;
                    h[4*q+3] = dA*h[4*q+3] + du*Bq.w; acc1 += h[4*q+3]*Cq.w; dA *= e1;
                }
            } else {
                #pragma unroll
                for (int q = 0; q < 4; q++) {
                    float4 Bq = Bv[q], Cq = Cv[q];
                    float dA;
                    dA = __expf(dt*a[4*q+0]); h[4*q+0] = dA*h[4*q+0] + du*Bq.x; acc0 += h[4*q+0]*Cq.x;
                    dA = __expf(dt*a[4*q+1]); h[4*q+1] = dA*h[4*q+1] + du*Bq.y; acc1 += h[4*q+1]*Cq.y;
                    dA = __expf(dt*a[4*q+2]); h[4*q+2] = dA*h[4*q+2] + du*Bq.z; acc0 += h[4*q+2]*Cq.z;
                    dA = __expf(dt*a[4*q+3]); h[4*q+3] = dA*h[4*q+3] + du*Bq.w; acc1 += h[4*q+3]*Cq.w;
                }
            }
            y[base + (size_t)t*DIN] = tf32r(((acc0 + acc1) + u*Dd) * silu_fast(z));
        }
    }
}

// ------------------------- output head + denorm -----------------------------
__global__ void out_kernel(const float* __restrict__ xn,
                           const float* __restrict__ out_w,
                           const float* __restrict__ mean,
                           const float* __restrict__ stdv,
                           float* __restrict__ out) {
    int t_out = blockIdx.x, b = blockIdx.y;
    int t = LBL + t_out;
    __shared__ float row[DM];
    for (int i = threadIdx.x; i < DM; i += blockDim.x)
        row[i] = xn[((size_t)(b*LSEQ + t))*DM + i];
    __syncthreads();
    int c = threadIdx.x >> 5;
    int lane = threadIdx.x & 31;
    if (c < CIN) {
        float acc = 0.f;
        for (int i = lane; i < DM; i += 32) acc += row[i] * out_w[c*DM + i];
        #pragma unroll
        for (int o = 16; o; o >>= 1) acc += __shfl_xor_sync(0xffffffffu, acc, o);
        if (lane == 0)
            out[(size_t)(b*PRED + t_out)*CIN + c] = acc * stdv[b*CIN + c] + mean[b*CIN + c];
    }
}

// ------------------------------- launcher -----------------------------------
extern "C" void kernel_launch(void* const* d_in, const int* in_sizes, int n_in,
                              void* d_out, int out_size) {
    const float* x_dec    = (const float*)d_in[2];
    const float* mark     = (const float*)d_in[3];
    const float* token_w  = (const float*)d_in[4];
    const float* timef_w  = (const float*)d_in[5];
    const float* norm_w   = (const float*)d_in[6];
    const float* norm_b   = (const float*)d_in[7];
    const float* in_proj_w= (const float*)d_in[8];
    const float* conv_w   = (const float*)d_in[9];
    const float* conv_b   = (const float*)d_in[10];
    const float* xproj_w  = (const float*)d_in[11];
    const float* dtproj_w = (const float*)d_in[12];
    const float* dtproj_b = (const float*)d_in[13];
    const float* A_log    = (const float*)d_in[14];
    const float* Dp       = (const float*)d_in[15];
    const float* outproj_w= (const float*)d_in[16];
    const float* fin_w    = (const float*)d_in[17];
    const float* fin_b    = (const float*)d_in[18];
    const float* out_w    = (const float*)d_in[19];
    float* out = (float*)d_out;

    float *px, *pxn, *pxz, *pxc, *pdbc, *py, *pmean, *pstd, *pwi, *pwo, *pa28, *pw28;
    cudaGetSymbolAddress((void**)&px,   g_x);
    cudaGetSymbolAddress((void**)&pxn,  g_xn);
    cudaGetSymbolAddress((void**)&pxz,  g_xz);
    cudaGetSymbolAddress((void**)&pxc,  g_xc);
    cudaGetSymbolAddress((void**)&pdbc, g_dbc);
    cudaGetSymbolAddress((void**)&py,   g_y);
    cudaGetSymbolAddress((void**)&pmean,g_mean);
    cudaGetSymbolAddress((void**)&pstd, g_std);
    cudaGetSymbolAddress((void**)&pwi,  g_wi);
    cudaGetSymbolAddress((void**)&pwo,  g_wo);
    cudaGetSymbolAddress((void**)&pa28, g_a28);
    cudaGetSymbolAddress((void**)&pw28, g_w28);

    const int SMEM_TC = 3*2*TILE*4;   // 61440 bytes
    cudaFuncSetAttribute(gemm_tc<0>, cudaFuncAttributeMaxDynamicSharedMemorySize, SMEM_TC);
    cudaFuncSetAttribute(gemm_tc<2>, cudaFuncAttributeMaxDynamicSharedMemorySize, SMEM_TC);

    // one-time prep
    {
        int ni = NLAYER*2*DIN*DM, no = NLAYER*DM*DIN;
        cvtw_kernel<<<(ni + 255)/256, 256>>>(in_proj_w, pwi, ni);
        cvtw_kernel<<<(no + 255)/256, 256>>>(outproj_w, pwo, no);
        w28_prep<<<(DM*KEMB + 255)/256, 256>>>(token_w, timef_w, pw28);
    }

    meanstd_kernel<<<1, 128>>>(x_dec, pmean, pstd);
    embed_prep<<<(NTOK*KEMB + 255)/256, 256>>>(x_dec, mark, pmean, pstd, pa28);
    // embed GEMM: (6144x28) @ (512x28)^T -> (6144x512)
    gemm_kernel<64,64,28,4,4><<<dim3(DM/64, NTOK/64, 1), 256>>>(
        pa28, KEMB, pw28, nullptr, px, DM, NTOK, DM, KEMB, KEMB, 0);

    for (int l = 0; l < NLAYER; l++) {
        ln_kernel<true><<<NTOK, 256>>>(px, norm_w + l*DM, norm_b + l*DM, pxn);
        // in_proj: (6144x512) @ (2048x512)^T -> (6144x2048)
        gemm_tc<0><<<dim3(2*DIN/128, NTOK/128), 256, SMEM_TC>>>(
            pxn, DM, pwi + (size_t)l*2*DIN*DM, pxz, 2*DIN, DM);
        dwconv_kernel<<<(NTOK*DIN)/256, 256>>>(pxz, conv_w + l*DIN*DCONV,
                                               conv_b + l*DIN, pxc);
        // x_proj: (6144x1024) @ (64x1024)^T -> (6144x64), split-K x4
        cudaMemsetAsync(pdbc, 0, (size_t)NTOK*64*sizeof(float));
        gemm_kernel<64,64,16,4,4><<<dim3(1, NTOK/64, 4), 256>>>(
            pxc, DIN, xproj_w + (size_t)l*64*DIN, nullptr, pdbc, 64,
            NTOK, 64, DIN, DIN/4, 3);
        // fused dt_proj + softplus + selective scan + gate
        dtscan_kernel<<<dim3(BB, DIN/128), 128>>>(
            pxc, pdbc, dtproj_w + (size_t)l*DIN*DTR, dtproj_b + l*DIN,
            A_log + (size_t)l*DIN*NST, Dp + l*DIN, pxz, py);
        // out_proj (+residual): (6144x1024) @ (512x1024)^T -> += x
        gemm_tc<2><<<dim3(DM/128, NTOK/128), 256, SMEM_TC>>>(
            py, DIN, pwo + (size_t)l*DM*DIN, px, DM, DIN);
    }

    ln_kernel<false><<<NTOK, 256>>>(px, fin_w, fin_b, pxn);
    out_kernel<<<dim3(PRED, BB), CIN*32>>>(pxn, out_w, pmean, pstd, out);
}

// round 9
// speedup vs baseline: 4.5793x; 1.7488x over previous
#include <cuda_runtime.h>
#include <cuda_bf16.h>
#include <stdint.h>
#include <math.h>

#define BB 16
#define LBL 48
#define PRED 336
#define LSEQ 384
#define CIN 7
#define TFD 4
#define DM 512
#define DIN 1024
#define NST 16
#define DTR 32
#define DCONV 4
#define NLAYER 2
#define EPSF 1e-5f

#define NTOK (BB*LSEQ)   // 6144 rows
#define KEMB 28

typedef __nv_bfloat16 bf16;

// ------------------- scratch (static device globals; no allocs) -------------
__device__ float g_x  [NTOK*DM];
__device__ float g_xn [NTOK*DM];
__device__ bf16  g_xnh[NTOK*DM];
__device__ float g_xz [NTOK*2*DIN];
__device__ float g_xc [NTOK*DIN];
__device__ float g_dbc[NTOK*64];
__device__ bf16  g_yh [NTOK*DIN];
__device__ float g_mean[BB*CIN];
__device__ float g_std [BB*CIN];
__device__ bf16  g_wih[NLAYER*2*DIN*DM];
__device__ bf16  g_woh[NLAYER*DM*DIN];
__device__ float g_a28[NTOK*KEMB];
__device__ float g_w28[DM*KEMB];

// ------------------------------- helpers ------------------------------------
__device__ __forceinline__ float block_reduce_sum(float v, float* red) {
    __syncthreads();
    int lane = threadIdx.x & 31, wid = threadIdx.x >> 5;
    #pragma unroll
    for (int o = 16; o; o >>= 1) v += __shfl_xor_sync(0xffffffffu, v, o);
    if (lane == 0) red[wid] = v;
    __syncthreads();
    if (wid == 0) {
        float t = (lane < (int)(blockDim.x >> 5)) ? red[lane] : 0.f;
        #pragma unroll
        for (int o = 16; o; o >>= 1) t += __shfl_xor_sync(0xffffffffu, t, o);
        if (lane == 0) red[0] = t;
    }
    __syncthreads();
    return red[0];
}

__device__ __forceinline__ float silu_fast(float x) {
    return __fdividef(x, 1.f + __expf(-x));
}

#define CP_ASYNC16(dst, src) \
    asm volatile("cp.async.cg.shared.global [%0], [%1], 16;" :: "r"(dst), "l"(src))

// --------------------- weight bf16 pre-conversion ---------------------------
__global__ void cvtwh_kernel(const float* __restrict__ src, bf16* __restrict__ dst, int n) {
    int i = blockIdx.x * 256 + threadIdx.x;
    if (i < n) dst[i] = __float2bfloat16(src[i]);
}

// --------------------- mean/std over label window ---------------------------
__global__ void meanstd_kernel(const float* __restrict__ x_dec,
                               float* __restrict__ mean, float* __restrict__ stdv) {
    int i = threadIdx.x;
    if (i >= BB*CIN) return;
    int b = i / CIN, c = i % CIN;
    float s = 0.f;
    for (int t = 0; t < LBL; t++) s += x_dec[(b*LSEQ + t)*CIN + c];
    float m = s / (float)LBL;
    float v = 0.f;
    for (int t = 0; t < LBL; t++) {
        float d = x_dec[(b*LSEQ + t)*CIN + c] - m;
        v += d*d;
    }
    v /= (float)LBL;
    mean[i] = m;
    stdv[i] = sqrtf(v + EPSF);
}

// ---------------- embed prep: window matrix + packed weights -----------------
__global__ void embed_prep(const float* __restrict__ x_dec,
                           const float* __restrict__ mark,
                           const float* __restrict__ mean,
                           const float* __restrict__ stdv,
                           float* __restrict__ A28) {
    int i = blockIdx.x * 256 + threadIdx.x;
    if (i >= NTOK*KEMB) return;
    int col = i % KEMB, tok = i / KEMB;
    int b = tok / LSEQ, t = tok % LSEQ;
    float v = 0.f;
    if (col < 21) {
        int c = col / 3, k = col % 3;
        int s = (t - 1 + k + LSEQ) % LSEQ;
        v = x_dec[(b*LSEQ + s)*CIN + c];
        if (s < LBL) v = (v - mean[b*CIN + c]) / stdv[b*CIN + c];
    } else if (col < 25) {
        v = mark[(b*LSEQ + t)*TFD + col - 21];
    }
    A28[i] = v;
}

__global__ void w28_prep(const float* __restrict__ token_w,
                         const float* __restrict__ timef_w,
                         float* __restrict__ W28) {
    int i = blockIdx.x * 256 + threadIdx.x;
    if (i >= DM*KEMB) return;
    int m = i / KEMB, j = i % KEMB;
    float v = 0.f;
    if (j < 21)      v = token_w[m*21 + j];
    else if (j < 25) v = timef_w[m*TFD + j - 21];
    W28[i] = v;
}

// --------------------------- layernorm (rows of DM) -------------------------
__global__ void lnf_kernel(const float* __restrict__ x,
                           const float* __restrict__ w,
                           const float* __restrict__ bb,
                           float* __restrict__ out) {
    __shared__ float red[32];
    int row = blockIdx.x;
    const float* xr = x + (size_t)row*DM;
    int tid = threadIdx.x;
    float v0 = xr[tid], v1 = xr[tid + 256];
    float s = block_reduce_sum(v0 + v1, red);
    float m = s * (1.f/(float)DM);
    float d0 = v0 - m, d1 = v1 - m;
    float vs = block_reduce_sum(d0*d0 + d1*d1, red);
    float inv = rsqrtf(vs * (1.f/(float)DM) + EPSF);
    out[(size_t)row*DM + tid]       = d0*inv*w[tid]       + bb[tid];
    out[(size_t)row*DM + tid + 256] = d1*inv*w[tid + 256] + bb[tid + 256];
}

__global__ void lnh_kernel(const float* __restrict__ x,
                           const float* __restrict__ w,
                           const float* __restrict__ bb,
                           bf16* __restrict__ out) {
    __shared__ float red[32];
    int row = blockIdx.x;
    const float* xr = x + (size_t)row*DM;
    int tid = threadIdx.x;
    float v0 = xr[tid], v1 = xr[tid + 256];
    float s = block_reduce_sum(v0 + v1, red);
    float m = s * (1.f/(float)DM);
    float d0 = v0 - m, d1 = v1 - m;
    float vs = block_reduce_sum(d0*d0 + d1*d1, red);
    float inv = rsqrtf(vs * (1.f/(float)DM) + EPSF);
    out[(size_t)row*DM + tid]       = __float2bfloat16(d0*inv*w[tid]       + bb[tid]);
    out[(size_t)row*DM + tid + 256] = __float2bfloat16(d1*inv*w[tid + 256] + bb[tid + 256]);
}

// ---------------------- BF16 tensor-core GEMM, cp.async 3-stage --------------
// C[M,N](f32) = A[M,K](bf16) @ W[N,K](bf16)^T.  MODE 0: store. MODE 2: C +=.
// BM=BN=128, BK=32, 3 stages, 256 threads (8 warps 4x2), warp tile 32x64.
#define SROWH 40
#define TILEH (128*SROWH)   // halves
template<int MODE>
__global__ void __launch_bounds__(256, 2) gemm_bf(const bf16* __restrict__ A, int lda,
                                                  const bf16* __restrict__ W,
                                                  float* __restrict__ C, int ldc,
                                                  int K) {
    extern __shared__ bf16 smh[];
    const int tid = threadIdx.x;
    const int lane = tid & 31, warp = tid >> 5;
    const int wm = warp >> 1, wn = warp & 1;
    const int row0 = blockIdx.y * 128, col0 = blockIdx.x * 128;
    const int KT = K >> 5;
    const unsigned sbase = (unsigned)__cvta_generic_to_shared(smh);

    float acc[2][8][4];
    #pragma unroll
    for (int i = 0; i < 2; i++)
        #pragma unroll
        for (int j = 0; j < 8; j++)
            #pragma unroll
            for (int q = 0; q < 4; q++) acc[i][j][q] = 0.f;

    #define ISSUE(kt_, s_) do {                                                 \
        int k0_ = (kt_) << 5;                                                   \
        _Pragma("unroll")                                                       \
        for (int h_ = 0; h_ < 2; h_++) {                                        \
            int c_ = tid + h_*256;                                              \
            int r_ = c_ >> 2, q_ = (c_ & 3) * 8;                                \
            const bf16* ga_ = A + (size_t)(row0 + r_)*lda + k0_ + q_;           \
            const bf16* gb_ = W + (size_t)(col0 + r_)*K   + k0_ + q_;           \
            unsigned da_ = sbase + (unsigned)(((s_)*2*TILEH + r_*SROWH + q_)*2);\
            unsigned db_ = sbase + (unsigned)(((s_)*2*TILEH + TILEH + r_*SROWH + q_)*2); \
            CP_ASYNC16(da_, ga_);                                               \
            CP_ASYNC16(db_, gb_);                                               \
        }                                                                       \
        asm volatile("cp.async.commit_group;");                                 \
    } while (0)

    ISSUE(0, 0);
    ISSUE(1, 1);

    for (int kt = 0; kt < KT; kt++) {
        if (kt + 2 < KT) asm volatile("cp.async.wait_group 1;");
        else             asm volatile("cp.async.wait_group 0;");
        __syncthreads();
        if (kt + 2 < KT) ISSUE(kt + 2, (kt + 2) % 3);

        const bf16* As_ = smh + (kt % 3) * 2 * TILEH;
        const bf16* Bs_ = As_ + TILEH;

        #pragma unroll
        for (int kk = 0; kk < 2; kk++) {
            const int kf2 = kk*16 + (lane & 3)*2;
            unsigned a0[2], a1[2], a2[2], a3[2];
            #pragma unroll
            for (int i = 0; i < 2; i++) {
                int r = wm*32 + i*16 + (lane >> 2);
                a0[i] = *(const unsigned*)(As_ + r*SROWH + kf2);
                a1[i] = *(const unsigned*)(As_ + (r+8)*SROWH + kf2);
                a2[i] = *(const unsigned*)(As_ + r*SROWH + kf2 + 8);
                a3[i] = *(const unsigned*)(As_ + (r+8)*SROWH + kf2 + 8);
            }
            #pragma unroll
            for (int j = 0; j < 8; j++) {
                int n = wn*64 + j*8 + (lane >> 2);
                unsigned b0 = *(const unsigned*)(Bs_ + n*SROWH + kf2);
                unsigned b1 = *(const unsigned*)(Bs_ + n*SROWH + kf2 + 8);
                #pragma unroll
                for (int i = 0; i < 2; i++) {
                    asm volatile(
                        "mma.sync.aligned.m16n8k16.row.col.f32.bf16.bf16.f32 "
                        "{%0,%1,%2,%3}, {%4,%5,%6,%7}, {%8,%9}, {%0,%1,%2,%3};"
                        : "+f"(acc[i][j][0]), "+f"(acc[i][j][1]),
                          "+f"(acc[i][j][2]), "+f"(acc[i][j][3])
                        : "r"(a0[i]), "r"(a1[i]), "r"(a2[i]), "r"(a3[i]),
                          "r"(b0), "r"(b1));
                }
            }
        }
    }
    #undef ISSUE

    #pragma unroll
    for (int i = 0; i < 2; i++) {
        int gr = row0 + wm*32 + i*16 + (lane >> 2);
        #pragma unroll
        for (int j = 0; j < 8; j++) {
            int gc = col0 + wn*64 + j*8 + (lane & 3)*2;
            float* p0 = C + (size_t)gr*ldc + gc;
            float* p1 = C + (size_t)(gr + 8)*ldc + gc;
            if (MODE == 2) {
                p0[0] += acc[i][j][0]; p0[1] += acc[i][j][1];
                p1[0] += acc[i][j][2]; p1[1] += acc[i][j][3];
            } else {
                p0[0] = acc[i][j][0]; p0[1] = acc[i][j][1];
                p1[0] = acc[i][j][2]; p1[1] = acc[i][j][3];
            }
        }
    }
}

// ------------------------------ SIMT GEMM ------------------------------------
// mode 0: store.  mode 3: atomicAdd (split-K).
template<int BM, int BN, int BK, int TM, int TN>
__global__ void gemm_kernel(const float* __restrict__ A, int lda,
                            const float* __restrict__ W,
                            const float* __restrict__ bias,
                            float* __restrict__ C, int ldc,
                            int M, int Nn, int K, int KC, int mode) {
    constexpr int THREADS = (BM/TM)*(BN/TN);
    __shared__ float As[BK][BM];
    __shared__ float Bs[BK][BN];
    int tid = threadIdx.x;
    int tx = tid % (BN/TN);
    int ty = tid / (BN/TN);
    int row0 = blockIdx.y * BM;
    int col0 = blockIdx.x * BN;
    int kbeg = blockIdx.z * KC;
    float acc[TM][TN];
    #pragma unroll
    for (int i = 0; i < TM; i++)
        #pragma unroll
        for (int j = 0; j < TN; j++) acc[i][j] = 0.f;

    for (int k0 = kbeg; k0 < kbeg + KC; k0 += BK) {
        #pragma unroll
        for (int i = tid; i < BM*BK; i += THREADS) {
            int m = i / BK, kk = i % BK;
            As[kk][m] = A[(size_t)(row0 + m)*lda + k0 + kk];
        }
        #pragma unroll
        for (int i = tid; i < BN*BK; i += THREADS) {
            int n = i / BK, kk = i % BK;
            Bs[kk][n] = W[(size_t)(col0 + n)*K + k0 + kk];
        }
        __syncthreads();
        #pragma unroll
        for (int kk = 0; kk < BK; kk++) {
            float a[TM], bfr[TN];
            #pragma unroll
            for (int i = 0; i < TM; i++) a[i] = As[kk][ty*TM + i];
            #pragma unroll
            for (int j = 0; j < TN; j++) bfr[j] = Bs[kk][tx*TN + j];
            #pragma unroll
            for (int i = 0; i < TM; i++)
                #pragma unroll
                for (int j = 0; j < TN; j++) acc[i][j] += a[i]*bfr[j];
        }
        __syncthreads();
    }
    #pragma unroll
    for (int i = 0; i < TM; i++) {
        int gm = row0 + ty*TM + i;
        #pragma unroll
        for (int j = 0; j < TN; j++) {
            int gn = col0 + tx*TN + j;
            float v = acc[i][j];
            if (mode == 3)      atomicAdd(&C[(size_t)gm*ldc + gn], v);
            else                C[(size_t)gm*ldc + gn] = v;
        }
    }
}

// -------------------- depthwise causal conv (k=4) + SiLU, float4 ------------
__global__ void dwconv_kernel(const float* __restrict__ xz,
                              const float* __restrict__ w,
                              const float* __restrict__ bias,
                              float* __restrict__ xc) {
    int gid = blockIdx.x * blockDim.x + threadIdx.x;   // over NTOK*DIN/4
    int d4 = gid % (DIN/4);
    int t  = (gid / (DIN/4)) % LSEQ;
    int b  = gid / ((DIN/4) * LSEQ);
    const float* xin = xz + (size_t)b * LSEQ * 2 * DIN + d4*4;
    float4 w0 = ((const float4*)w)[d4*4 + 0];
    float4 w1 = ((const float4*)w)[d4*4 + 1];
    float4 w2 = ((const float4*)w)[d4*4 + 2];
    float4 w3 = ((const float4*)w)[d4*4 + 3];
    float4 acc = ((const float4*)bias)[d4];
    #pragma unroll
    for (int k = 0; k < DCONV; k++) {
        int s = t - (DCONV-1) + k;
        if (s >= 0) {
            float4 xv = *(const float4*)(xin + (size_t)s*2*DIN);
            float wk0 = (&w0.x)[k], wk1 = (&w1.x)[k], wk2 = (&w2.x)[k], wk3 = (&w3.x)[k];
            acc.x += xv.x*wk0; acc.y += xv.y*wk1; acc.z += xv.z*wk2; acc.w += xv.w*wk3;
        }
    }
    acc.x = silu_fast(acc.x); acc.y = silu_fast(acc.y);
    acc.z = silu_fast(acc.z); acc.w = silu_fast(acc.w);
    ((float4*)xc)[gid] = acc;
}

// --------------- fused dt_proj + softplus + selective scan ------------------
// thread = (b, d); dbc/xc/z chunks double-buffered in smem via cp.async.
#define CH 32
#define NCH (LSEQ/CH)
#define DBC_OFF(bu) ((bu)*CH*64)
#define XC_OFF(bu)  (2*CH*64 + (bu)*CH*128)
#define ZZ_OFF(bu)  (2*CH*64 + 2*CH*128 + (bu)*CH*128)
#define SCAN_SMEM ((2*CH*64 + 4*CH*128)*4)
__global__ void __launch_bounds__(128) dtscan_kernel(
    const float* __restrict__ xc,
    const float* __restrict__ dbc,
    const float* __restrict__ dtw,   // (DIN, DTR)
    const float* __restrict__ dtb,   // (DIN)
    const float* __restrict__ A_log, // (DIN, NST)
    const float* __restrict__ Dp,    // (DIN)
    const float* __restrict__ xz,    // z at +DIN
    bf16* __restrict__ y) {
    extern __shared__ float smf[];
    const unsigned sbase = (unsigned)__cvta_generic_to_shared(smf);
    int b = blockIdx.x;
    int d0 = blockIdx.y * 128;
    int d = d0 + threadIdx.x;
    float h[NST], a[NST], w[DTR];
    #pragma unroll
    for (int n = 0; n < NST; n++) {
        h[n] = 0.f;
        a[n] = -__expf(A_log[d*NST + n]);
    }
    #pragma unroll
    for (int j = 0; j < DTR; j++) w[j] = dtw[d*DTR + j];
    float bias = dtb[d], Dd = Dp[d];
    bool geom = true;
    #pragma unroll
    for (int n = 1; n < NST; n++) {
        float pred = (float)(n+1) * a[0];
        if (fabsf(a[n] - pred) > 1e-4f * fmaxf(1.f, fabsf(a[n]))) geom = false;
    }
    const float* dbc_b = dbc + (size_t)b * LSEQ * 64;
    const float* xcb   = xc + (size_t)b * LSEQ * DIN + d0;
    const float* zzb   = xz + (size_t)b * LSEQ * 2 * DIN + DIN + d0;
    size_t ybase = (size_t)b * LSEQ * DIN + d;

    #define PRE(c_, bu_) do {                                                   \
        int t0_ = (c_)*CH;                                                      \
        for (int i_ = threadIdx.x; i_ < CH*16; i_ += 128) {                     \
            int tt_ = i_ >> 4, q_ = (i_ & 15) * 4;                              \
            CP_ASYNC16(sbase + (unsigned)((DBC_OFF(bu_) + tt_*64 + q_)*4),      \
                       dbc_b + (size_t)(t0_+tt_)*64 + q_);                      \
        }                                                                       \
        for (int i_ = threadIdx.x; i_ < CH*32; i_ += 128) {                     \
            int tt_ = i_ >> 5, q_ = (i_ & 31) * 4;                              \
            CP_ASYNC16(sbase + (unsigned)((XC_OFF(bu_) + tt_*128 + q_)*4),      \
                       xcb + (size_t)(t0_+tt_)*DIN + q_);                       \
            CP_ASYNC16(sbase + (unsigned)((ZZ_OFF(bu_) + tt_*128 + q_)*4),      \
                       zzb + (size_t)(t0_+tt_)*2*DIN + q_);                     \
        }                                                                       \
        asm volatile("cp.async.commit_group;");                                 \
    } while (0)

    PRE(0, 0);
    int bu = 0;
    for (int c = 0; c < NCH; c++) {
        asm volatile("cp.async.wait_group 0;");
        __syncthreads();
        if (c + 1 < NCH) PRE(c + 1, bu ^ 1);
        const float* dchunk = smf + DBC_OFF(bu);
        const float* xchunk = smf + XC_OFF(bu);
        const float* zchunk = smf + ZZ_OFF(bu);
        for (int tt = 0; tt < CH; tt++) {
            float u  = xchunk[tt*128 + threadIdx.x];
            float zv = zchunk[tt*128 + threadIdx.x];
            const float4* dr = (const float4*)(dchunk + tt*64);
            // dt_proj: 4 independent partial chains
            float v0 = bias, v1 = 0.f, v2 = 0.f, v3 = 0.f;
            #pragma unroll
            for (int j = 0; j < 2; j++) {
                float4 q0 = dr[4*j], q1 = dr[4*j+1], q2 = dr[4*j+2], q3 = dr[4*j+3];
                v0 += w[16*j+ 0]*q0.x + w[16*j+ 1]*q0.y + w[16*j+ 2]*q0.z + w[16*j+ 3]*q0.w;
                v1 += w[16*j+ 4]*q1.x + w[16*j+ 5]*q1.y + w[16*j+ 6]*q1.z + w[16*j+ 7]*q1.w;
                v2 += w[16*j+ 8]*q2.x + w[16*j+ 9]*q2.y + w[16*j+10]*q2.z + w[16*j+11]*q2.w;
                v3 += w[16*j+12]*q3.x + w[16*j+13]*q3.y + w[16*j+14]*q3.z + w[16*j+15]*q3.w;
            }
            float v = (v0 + v1) + (v2 + v3);
            float dt = (v > 20.f) ? v : __logf(1.f + __expf(v));
            float du = dt * u;
            const float4* Bv = (const float4*)(dchunk + tt*64 + DTR);
            const float4* Cv = (const float4*)(dchunk + tt*64 + DTR + NST);
            float dA[NST];
            if (geom) {
                float p1 = __expf(dt * a[0]);
                float p2 = p1*p1, p3 = p2*p1, p4 = p2*p2;
                float p5 = p4*p1, p6 = p4*p2, p7 = p4*p3, p8 = p4*p4;
                dA[0]=p1; dA[1]=p2; dA[2]=p3; dA[3]=p4;
                dA[4]=p5; dA[5]=p6; dA[6]=p7; dA[7]=p8;
                dA[8]=p8*p1; dA[9]=p8*p2; dA[10]=p8*p3; dA[11]=p8*p4;
                dA[12]=p8*p5; dA[13]=p8*p6; dA[14]=p8*p7; dA[15]=p8*p8;
            } else {
                #pragma unroll
                for (int n = 0; n < NST; n++) dA[n] = __expf(dt * a[n]);
            }
            float acc0 = 0.f, acc1 = 0.f;
            #pragma unroll
            for (int q = 0; q < 4; q++) {
                float4 Bq = Bv[q], Cq = Cv[q];
                h[4*q+0] = dA[4*q+0]*h[4*q+0] + du*Bq.x; acc0 += h[4*q+0]*Cq.x;
                h[4*q+1] = dA[4*q+1]*h[4*q+1] + du*Bq.y; acc1 += h[4*q+1]*Cq.y;
                h[4*q+2] = dA[4*q+2]*h[4*q+2] + du*Bq.z; acc0 += h[4*q+2]*Cq.z;
                h[4*q+3] = dA[4*q+3]*h[4*q+3] + du*Bq.w; acc1 += h[4*q+3]*Cq.w;
            }
            int t = c*CH + tt;
            y[ybase + (size_t)t*DIN] =
                __float2bfloat16(((acc0 + acc1) + u*Dd) * silu_fast(zv));
        }
        bu ^= 1;
    }
    #undef PRE
}

// ------------------------- output head + denorm -----------------------------
__global__ void out_kernel(const float* __restrict__ xn,
                           const float* __restrict__ out_w,
                           const float* __restrict__ mean,
                           const float* __restrict__ stdv,
                           float* __restrict__ out) {
    int t_out = blockIdx.x, b = blockIdx.y;
    int t = LBL + t_out;
    __shared__ float row[DM];
    for (int i = threadIdx.x; i < DM; i += blockDim.x)
        row[i] = xn[((size_t)(b*LSEQ + t))*DM + i];
    __syncthreads();
    int c = threadIdx.x >> 5;
    int lane = threadIdx.x & 31;
    if (c < CIN) {
        float acc = 0.f;
        for (int i = lane; i < DM; i += 32) acc += row[i] * out_w[c*DM + i];
        #pragma unroll
        for (int o = 16; o; o >>= 1) acc += __shfl_xor_sync(0xffffffffu, acc, o);
        if (lane == 0)
            out[(size_t)(b*PRED + t_out)*CIN + c] = acc * stdv[b*CIN + c] + mean[b*CIN + c];
    }
}

// ------------------------------- launcher -----------------------------------
extern "C" void kernel_launch(void* const* d_in, const int* in_sizes, int n_in,
                              void* d_out, int out_size) {
    const float* x_dec    = (const float*)d_in[2];
    const float* mark     = (const float*)d_in[3];
    const float* token_w  = (const float*)d_in[4];
    const float* timef_w  = (const float*)d_in[5];
    const float* norm_w   = (const float*)d_in[6];
    const float* norm_b   = (const float*)d_in[7];
    const float* in_proj_w= (const float*)d_in[8];
    const float* conv_w   = (const float*)d_in[9];
    const float* conv_b   = (const float*)d_in[10];
    const float* xproj_w  = (const float*)d_in[11];
    const float* dtproj_w = (const float*)d_in[12];
    const float* dtproj_b = (const float*)d_in[13];
    const float* A_log    = (const float*)d_in[14];
    const float* Dp       = (const float*)d_in[15];
    const float* outproj_w= (const float*)d_in[16];
    const float* fin_w    = (const float*)d_in[17];
    const float* fin_b    = (const float*)d_in[18];
    const float* out_w    = (const float*)d_in[19];
    float* out = (float*)d_out;

    float *px, *pxn, *pxz, *pxc, *pdbc, *pmean, *pstd, *pa28, *pw28;
    bf16 *pxnh, *pyh, *pwih, *pwoh;
    cudaGetSymbolAddress((void**)&px,   g_x);
    cudaGetSymbolAddress((void**)&pxn,  g_xn);
    cudaGetSymbolAddress((void**)&pxnh, g_xnh);
    cudaGetSymbolAddress((void**)&pxz,  g_xz);
    cudaGetSymbolAddress((void**)&pxc,  g_xc);
    cudaGetSymbolAddress((void**)&pdbc, g_dbc);
    cudaGetSymbolAddress((void**)&pyh,  g_yh);
    cudaGetSymbolAddress((void**)&pmean,g_mean);
    cudaGetSymbolAddress((void**)&pstd, g_std);
    cudaGetSymbolAddress((void**)&pwih, g_wih);
    cudaGetSymbolAddress((void**)&pwoh, g_woh);
    cudaGetSymbolAddress((void**)&pa28, g_a28);
    cudaGetSymbolAddress((void**)&pw28, g_w28);

    const int SMEM_TC = 3*2*TILEH*2;   // 61440 bytes
    cudaFuncSetAttribute(gemm_bf<0>, cudaFuncAttributeMaxDynamicSharedMemorySize, SMEM_TC);
    cudaFuncSetAttribute(gemm_bf<2>, cudaFuncAttributeMaxDynamicSharedMemorySize, SMEM_TC);
    cudaFuncSetAttribute(dtscan_kernel, cudaFuncAttributeMaxDynamicSharedMemorySize, SCAN_SMEM);

    // one-time prep
    {
        int ni = NLAYER*2*DIN*DM, no = NLAYER*DM*DIN;
        cvtwh_kernel<<<(ni + 255)/256, 256>>>(in_proj_w, pwih, ni);
        cvtwh_kernel<<<(no + 255)/256, 256>>>(outproj_w, pwoh, no);
        w28_prep<<<(DM*KEMB + 255)/256, 256>>>(token_w, timef_w, pw28);
    }

    meanstd_kernel<<<1, 128>>>(x_dec, pmean, pstd);
    embed_prep<<<(NTOK*KEMB + 255)/256, 256>>>(x_dec, mark, pmean, pstd, pa28);
    // embed GEMM: (6144x28) @ (512x28)^T -> (6144x512)
    gemm_kernel<64,64,28,4,4><<<dim3(DM/64, NTOK/64, 1), 256>>>(
        pa28, KEMB, pw28, nullptr, px, DM, NTOK, DM, KEMB, KEMB, 0);

    for (int l = 0; l < NLAYER; l++) {
        lnh_kernel<<<NTOK, 256>>>(px, norm_w + l*DM, norm_b + l*DM, pxnh);
        // in_proj: (6144x512) @ (2048x512)^T -> (6144x2048)
        gemm_bf<0><<<dim3(2*DIN/128, NTOK/128), 256, SMEM_TC>>>(
            pxnh, DM, pwih + (size_t)l*2*DIN*DM, pxz, 2*DIN, DM);
        dwconv_kernel<<<(NTOK*DIN/4)/256, 256>>>(pxz, conv_w + l*DIN*DCONV,
                                                 conv_b + l*DIN, pxc);
        // x_proj: (6144x1024) @ (64x1024)^T -> (6144x64), split-K x4
        cudaMemsetAsync(pdbc, 0, (size_t)NTOK*64*sizeof(float));
        gemm_kernel<64,64,16,4,4><<<dim3(1, NTOK/64, 4), 256>>>(
            pxc, DIN, xproj_w + (size_t)l*64*DIN, nullptr, pdbc, 64,
            NTOK, 64, DIN, DIN/4, 3);
        // fused dt_proj + softplus + selective scan + gate
        dtscan_kernel<<<dim3(BB, DIN/128), 128, SCAN_SMEM>>>(
            pxc, pdbc, dtproj_w + (size_t)l*DIN*DTR, dtproj_b + l*DIN,
            A_log + (size_t)l*DIN*NST, Dp + l*DIN, pxz, pyh);
        // out_proj (+residual): (6144x1024) @ (512x1024)^T -> += x
        gemm_bf<2><<<dim3(DM/128, NTOK/128), 256, SMEM_TC>>>(
            pyh, DIN, pwoh + (size_t)l*DM*DIN, px, DM, DIN);
    }

    lnf_kernel<<<NTOK, 256>>>(px, fin_w, fin_b, pxn);
    out_kernel<<<dim3(PRED, BB), CIN*32>>>(pxn, out_w, pmean, pstd, out);
}